// round 5
// baseline (speedup 1.0000x reference)
#include <cuda_runtime.h>
#include <cuda_bf16.h>
#include <cstdint>

// ============================================================================
// MLPList: B=32768 rows, 63 stacked MLPs (64->64->64->1), causal input mask.
// R5: i-major grid (one MLP index per CTA, two 128-row tiles each). Weights
// staged once per CTA; X tile loaded raw and split to bf16 hi/lo IN PLACE.
// 66KB smem/CTA -> 3 CTAs/SM (12 warps) to fill the HMMA pipe.
// ============================================================================
#define NI 63
#define DK 64
#define HN 64

__device__ __align__(16) unsigned char g_wpack[NI * 32768]; // W1hi,W1lo,W2hi,W2lo (8KB each)
__device__ __align__(16) float g_bpack[NI * 208];           // b1[64], b2[64], w3[64], b3, pad
__device__ float g_o0;

// ---------------------------------------------------------------------------
__device__ __forceinline__ uint32_t smem_u32(const void* p) {
    uint32_t a;
    asm("{ .reg .u64 t; cvta.to.shared.u64 t, %1; cvt.u32.u64 %0, t; }"
        : "=r"(a) : "l"(p));
    return a;
}

__device__ __forceinline__ void split2(float a, float b, uint32_t& hi, uint32_t& lo) {
    __nv_bfloat16 ha = __float2bfloat16(a), hb = __float2bfloat16(b);
    float ra = a - __bfloat162float(ha);
    float rb = b - __bfloat162float(hb);
    __nv_bfloat16 la = __float2bfloat16(ra), lb = __float2bfloat16(rb);
    hi = ((uint32_t)__bfloat16_as_ushort(hb) << 16) | (uint32_t)__bfloat16_as_ushort(ha);
    lo = ((uint32_t)__bfloat16_as_ushort(lb) << 16) | (uint32_t)__bfloat16_as_ushort(la);
}

__device__ __forceinline__ void mma16816(float* d, const uint32_t* a, const uint32_t* b) {
    asm volatile(
        "mma.sync.aligned.m16n8k16.row.col.f32.bf16.bf16.f32 "
        "{%0,%1,%2,%3}, {%4,%5,%6,%7}, {%8,%9}, {%0,%1,%2,%3};"
        : "+f"(d[0]), "+f"(d[1]), "+f"(d[2]), "+f"(d[3])
        : "r"(a[0]), "r"(a[1]), "r"(a[2]), "r"(a[3]), "r"(b[0]), "r"(b[1]));
}

// ============================================================================
// Prep kernels (unchanged layouts)
// ============================================================================
__global__ void prep_weights_kernel(const float* __restrict__ W1,
                                    const float* __restrict__ W2) {
    int idx = blockIdx.x * blockDim.x + threadIdx.x;
    if (idx >= NI * DK * HN) return;
    int i = idx >> 12;
    int n = (idx >> 6) & 63;
    int k = idx & 63;
    uint32_t off = (uint32_t)(n * 128) + (uint32_t)((k * 2) ^ ((n & 7) << 4));
    unsigned char* base = g_wpack + (size_t)i * 32768;

    float v1 = (k <= i) ? W1[((size_t)i * DK + k) * HN + n] : 0.0f;
    __nv_bfloat16 h1 = __float2bfloat16(v1);
    __nv_bfloat16 l1 = __float2bfloat16(v1 - __bfloat162float(h1));
    *(__nv_bfloat16*)(base + 0 * 8192 + off) = h1;
    *(__nv_bfloat16*)(base + 1 * 8192 + off) = l1;

    float v2 = W2[((size_t)i * HN + k) * HN + n];
    __nv_bfloat16 h2 = __float2bfloat16(v2);
    __nv_bfloat16 l2 = __float2bfloat16(v2 - __bfloat162float(h2));
    *(__nv_bfloat16*)(base + 2 * 8192 + off) = h2;
    *(__nv_bfloat16*)(base + 3 * 8192 + off) = l2;
}

__global__ void prep_bias_kernel(const float* __restrict__ b1, const float* __restrict__ b2,
                                 const float* __restrict__ W3, const float* __restrict__ b3) {
    int idx = blockIdx.x * blockDim.x + threadIdx.x;
    if (idx >= NI * 208) return;
    int i = idx / 208, t = idx % 208;
    float v = 0.0f;
    if (t < 64)       v = b1[i * 64 + t];
    else if (t < 128) v = b2[i * 64 + (t - 64)];
    else if (t < 192) v = W3[i * 64 + (t - 128)];
    else if (t == 192) v = b3[i];
    g_bpack[i * 208 + t] = v;
}

__global__ void prep_dim0_kernel(const float* __restrict__ w01, const float* __restrict__ b01,
                                 const float* __restrict__ w02, const float* __restrict__ b02,
                                 const float* __restrict__ w03, const float* __restrict__ b03) {
    __shared__ float h0s[64];
    __shared__ float ps[64];
    int h = threadIdx.x;
    float a = b01[h];
#pragma unroll
    for (int t = 0; t < 10; t++) {
        float v = 0.1f * (-5.0f + (float)t * (10.0f / 9.0f));
        a = fmaf(v, w01[t * 64 + h], a);
    }
    h0s[h] = fmaxf(a, 0.0f);
    __syncthreads();
    float a2 = b02[h];
#pragma unroll
    for (int k = 0; k < 64; k++) a2 = fmaf(h0s[k], w02[k * 64 + h], a2);
    ps[h] = fmaxf(a2, 0.0f) * w03[h];
    __syncthreads();
    if (h == 0) {
        float s = b03[0];
        for (int k = 0; k < 64; k++) s += ps[k];
        g_o0 = s;
    }
}

// ============================================================================
// Main kernel
// ============================================================================
// SMEM: [0,32768)   X region: raw fp32 tile (128x64), then in-place bf16
//                   hi tile at +0 (16KB) and lo tile at +16384 (16KB)
//       [32768,65536) W image: W1hi,W1lo,W2hi,W2lo (8KB each)
//       [65536,66368) bias pack (832B)
constexpr int OFF_X    = 0;
constexpr int OFF_W    = 32768;
constexpr int OFF_BIAS = 65536;
constexpr int SMEM_BYTES = 66432;

__global__ void __launch_bounds__(128, 3)
mlplist_main_kernel(const float* __restrict__ x, float* __restrict__ out, int B) {
    extern __shared__ char smem[];
    const int tid  = threadIdx.x;
    const int warp = tid >> 5, lane = tid & 31;
    const int tig  = lane & 3, grp = lane >> 2;
    const uint32_t sw = (uint32_t)grp << 4;
    const int i    = blockIdx.y;
    const int pair = blockIdx.x;
    const float o0 = g_o0;

    const char*  Wb   = smem + OFF_W;
    const float* bias = (const float*)(smem + OFF_BIAS);
    const uint32_t xdst = smem_u32(smem + OFF_X);

    // ---- prologue: stage W image + bias + first X tile ----
    {
        const unsigned char* wsrc = g_wpack + (size_t)i * 32768;
        uint32_t wdst = smem_u32(smem + OFF_W);
#pragma unroll
        for (int j = 0; j < 16; j++) {
            int c = tid + j * 128;
            asm volatile("cp.async.cg.shared.global [%0], [%1], 16;"
                         :: "r"(wdst + c * 16), "l"(wsrc + (size_t)c * 16));
        }
        if (tid < 52) {
            const float* bsrc = g_bpack + (size_t)i * 208;
            asm volatile("cp.async.cg.shared.global [%0], [%1], 16;"
                         :: "r"(smem_u32(smem + OFF_BIAS) + tid * 16),
                            "l"((const char*)bsrc + tid * 16));
        }
    }

    for (int t = 0; t < 2; t++) {
        const int tileBase = (pair * 2 + t) * 128;
        if (tileBase >= B) break;

        // ---- stage raw X tile (32KB, clamped addresses for safety) ----
        {
            const float* src = x + (size_t)tileBase * DK;
            const long maxc = ((long)(B - tileBase) * DK) / 4 - 1;  // last valid 16B chunk
#pragma unroll
            for (int j = 0; j < 16; j++) {
                long c = tid + j * 128;
                long cs = c <= maxc ? c : maxc;
                asm volatile("cp.async.cg.shared.global [%0], [%1], 16;"
                             :: "r"(xdst + (uint32_t)c * 16), "l"(src + cs * 4));
            }
            asm volatile("cp.async.commit_group;" ::: "memory");
            asm volatile("cp.async.wait_group 0;" ::: "memory");
        }
        __syncthreads();

        // ---- in-place split: raw fp32 row -> bf16 hi/lo swizzled tiles ----
        {
            float v[64];
            const float4* raw = (const float4*)(smem + OFF_X) + tid * 16;
#pragma unroll
            for (int c = 0; c < 16; c++) {
                float4 f = raw[c];
                v[4 * c] = f.x; v[4 * c + 1] = f.y; v[4 * c + 2] = f.z; v[4 * c + 3] = f.w;
            }
            __syncthreads();   // all raw reads done before overwrite
#pragma unroll
            for (int c = 0; c < 8; c++) {
                uint4 hp, lp;
                split2(v[8 * c + 0], v[8 * c + 1], hp.x, lp.x);
                split2(v[8 * c + 2], v[8 * c + 3], hp.y, lp.y);
                split2(v[8 * c + 4], v[8 * c + 5], hp.z, lp.z);
                split2(v[8 * c + 6], v[8 * c + 7], hp.w, lp.w);
                uint32_t off = (uint32_t)(tid * 128) + (uint32_t)((c * 16) ^ ((tid & 7) << 4));
                *(uint4*)(smem + OFF_X + off) = hp;
                *(uint4*)(smem + OFF_X + 16384 + off) = lp;
            }
        }
        __syncthreads();

        const float* b1v = bias, * b2v = bias + 64, * w3v = bias + 128;
        const float  b3v = bias[192];

        float acc[2][8][4];
#pragma unroll
        for (int m = 0; m < 2; m++)
#pragma unroll
            for (int j = 0; j < 8; j++)
#pragma unroll
                for (int r = 0; r < 4; r++) acc[m][j][r] = 0.0f;

        // ---- Layer 1: acc += Xsplit @ W1split^T (masked K chunks skipped) ----
        const int kt1 = (i >> 4) + 1;
        for (int kt = 0; kt < kt1; kt++) {
            const uint32_t k0 = (uint32_t)(kt * 32 + tig * 4);
            uint32_t aH[2][4], aL[2][4];
#pragma unroll
            for (int m = 0; m < 2; m++) {
                const int r0 = warp * 32 + m * 16 + grp, r1 = r0 + 8;
                const uint32_t o00 = r0 * 128 + (k0 ^ sw);
                const uint32_t o10 = r1 * 128 + (k0 ^ sw);
                const uint32_t o01 = r0 * 128 + ((k0 + 16) ^ sw);
                const uint32_t o11 = r1 * 128 + ((k0 + 16) ^ sw);
                aH[m][0] = *(const uint32_t*)(smem + OFF_X + o00);
                aH[m][1] = *(const uint32_t*)(smem + OFF_X + o10);
                aH[m][2] = *(const uint32_t*)(smem + OFF_X + o01);
                aH[m][3] = *(const uint32_t*)(smem + OFF_X + o11);
                aL[m][0] = *(const uint32_t*)(smem + OFF_X + 16384 + o00);
                aL[m][1] = *(const uint32_t*)(smem + OFF_X + 16384 + o10);
                aL[m][2] = *(const uint32_t*)(smem + OFF_X + 16384 + o01);
                aL[m][3] = *(const uint32_t*)(smem + OFF_X + 16384 + o11);
            }
#pragma unroll
            for (int g = 0; g < 2; g++) {
                uint32_t bH[4][2], bL[4][2];
#pragma unroll
                for (int jj = 0; jj < 4; jj++) {
                    const int n = (g * 4 + jj) * 8 + grp;
                    const uint32_t ob0 = n * 128 + (k0 ^ sw);
                    const uint32_t ob1 = n * 128 + ((k0 + 16) ^ sw);
                    bH[jj][0] = *(const uint32_t*)(Wb + 0 * 8192 + ob0);
                    bH[jj][1] = *(const uint32_t*)(Wb + 0 * 8192 + ob1);
                    bL[jj][0] = *(const uint32_t*)(Wb + 1 * 8192 + ob0);
                    bL[jj][1] = *(const uint32_t*)(Wb + 1 * 8192 + ob1);
                }
#pragma unroll
                for (int jj = 0; jj < 4; jj++) {
                    const int j = g * 4 + jj;
                    mma16816(acc[0][j], aH[0], bH[jj]);
                    mma16816(acc[1][j], aH[1], bH[jj]);
                }
#pragma unroll
                for (int jj = 0; jj < 4; jj++) {
                    const int j = g * 4 + jj;
                    mma16816(acc[0][j], aH[0], bL[jj]);
                    mma16816(acc[1][j], aH[1], bL[jj]);
                }
#pragma unroll
                for (int jj = 0; jj < 4; jj++) {
                    const int j = g * 4 + jj;
                    mma16816(acc[0][j], aL[0], bH[jj]);
                    mma16816(acc[1][j], aL[1], bH[jj]);
                }
            }
        }

        // ---- bias + relu + split -> layer-2 A fragments (registers only) ----
        uint32_t A2H[2][4][4], A2L[2][4][4];
#pragma unroll
        for (int m = 0; m < 2; m++)
#pragma unroll
            for (int k2 = 0; k2 < 4; k2++) {
                const int j0 = 2 * k2, j1 = 2 * k2 + 1;
                const int c0 = j0 * 8 + 2 * tig;
                const int c1 = j1 * 8 + 2 * tig;
                const float bb00 = b1v[c0], bb01 = b1v[c0 + 1];
                const float bb10 = b1v[c1], bb11 = b1v[c1 + 1];
                float v00 = fmaxf(acc[m][j0][0] + bb00, 0.f);
                float v01 = fmaxf(acc[m][j0][1] + bb01, 0.f);
                float v02 = fmaxf(acc[m][j0][2] + bb00, 0.f);
                float v03 = fmaxf(acc[m][j0][3] + bb01, 0.f);
                float v10 = fmaxf(acc[m][j1][0] + bb10, 0.f);
                float v11 = fmaxf(acc[m][j1][1] + bb11, 0.f);
                float v12 = fmaxf(acc[m][j1][2] + bb10, 0.f);
                float v13 = fmaxf(acc[m][j1][3] + bb11, 0.f);
                split2(v00, v01, A2H[m][k2][0], A2L[m][k2][0]);
                split2(v02, v03, A2H[m][k2][1], A2L[m][k2][1]);
                split2(v10, v11, A2H[m][k2][2], A2L[m][k2][2]);
                split2(v12, v13, A2H[m][k2][3], A2L[m][k2][3]);
            }

        // ---- Layer 2 ----
#pragma unroll
        for (int m = 0; m < 2; m++)
#pragma unroll
            for (int j = 0; j < 8; j++)
#pragma unroll
                for (int r = 0; r < 4; r++) acc[m][j][r] = 0.0f;

#pragma unroll
        for (int k2 = 0; k2 < 4; k2++) {
            const uint32_t k0 = (uint32_t)(k2 * 32 + tig * 4);
#pragma unroll
            for (int g = 0; g < 2; g++) {
                uint32_t bH[4][2], bL[4][2];
#pragma unroll
                for (int jj = 0; jj < 4; jj++) {
                    const int n = (g * 4 + jj) * 8 + grp;
                    const uint32_t ob0 = n * 128 + (k0 ^ sw);
                    const uint32_t ob1 = n * 128 + ((k0 + 16) ^ sw);
                    bH[jj][0] = *(const uint32_t*)(Wb + 2 * 8192 + ob0);
                    bH[jj][1] = *(const uint32_t*)(Wb + 2 * 8192 + ob1);
                    bL[jj][0] = *(const uint32_t*)(Wb + 3 * 8192 + ob0);
                    bL[jj][1] = *(const uint32_t*)(Wb + 3 * 8192 + ob1);
                }
#pragma unroll
                for (int jj = 0; jj < 4; jj++) {
                    const int j = g * 4 + jj;
                    mma16816(acc[0][j], A2H[0][k2], bH[jj]);
                    mma16816(acc[1][j], A2H[1][k2], bH[jj]);
                }
#pragma unroll
                for (int jj = 0; jj < 4; jj++) {
                    const int j = g * 4 + jj;
                    mma16816(acc[0][j], A2H[0][k2], bL[jj]);
                    mma16816(acc[1][j], A2H[1][k2], bL[jj]);
                }
#pragma unroll
                for (int jj = 0; jj < 4; jj++) {
                    const int j = g * 4 + jj;
                    mma16816(acc[0][j], A2L[0][k2], bH[jj]);
                    mma16816(acc[1][j], A2L[1][k2], bH[jj]);
                }
            }
        }

        // ---- Layer 3: bias + relu + dot(w3) + quad reduce + store ----
#pragma unroll
        for (int m = 0; m < 2; m++) {
            float p0 = 0.f, p1 = 0.f;
#pragma unroll
            for (int j = 0; j < 8; j++) {
                const int c = 8 * j + 2 * tig;
                const float w0 = w3v[c], w1 = w3v[c + 1];
                const float bb0 = b2v[c], bb1 = b2v[c + 1];
                p0 += fmaxf(acc[m][j][0] + bb0, 0.f) * w0
                    + fmaxf(acc[m][j][1] + bb1, 0.f) * w1;
                p1 += fmaxf(acc[m][j][2] + bb0, 0.f) * w0
                    + fmaxf(acc[m][j][3] + bb1, 0.f) * w1;
            }
            p0 += __shfl_xor_sync(0xFFFFFFFFu, p0, 1);
            p0 += __shfl_xor_sync(0xFFFFFFFFu, p0, 2);
            p1 += __shfl_xor_sync(0xFFFFFFFFu, p1, 1);
            p1 += __shfl_xor_sync(0xFFFFFFFFu, p1, 2);
            if (tig == 0) {
                const int row = tileBase + warp * 32 + m * 16 + grp;
                if (row < B)     out[(size_t)row * 64 + (i + 1)]       = p0 + b3v;
                if (row + 8 < B) out[(size_t)(row + 8) * 64 + (i + 1)] = p1 + b3v;
            }
        }

        // dim-0 column (batch-constant), written once per row by the i==0 CTAs
        if (i == 0 && tileBase + tid < B) out[(size_t)(tileBase + tid) * 64] = o0;

        if (t == 0) __syncthreads();   // all reads of X region done before reload
    }
}

// ============================================================================
// Launch
// ============================================================================
extern "C" void kernel_launch(void* const* d_in, const int* in_sizes, int n_in,
                              void* d_out, int out_size) {
    const float* x   = (const float*)d_in[0];
    const float* W1  = (const float*)d_in[1];
    const float* b1  = (const float*)d_in[2];
    const float* W2  = (const float*)d_in[3];
    const float* b2  = (const float*)d_in[4];
    const float* W3  = (const float*)d_in[5];
    const float* b3  = (const float*)d_in[6];
    const float* w01 = (const float*)d_in[7];
    const float* b01 = (const float*)d_in[8];
    const float* w02 = (const float*)d_in[9];
    const float* b02 = (const float*)d_in[10];
    const float* w03 = (const float*)d_in[11];
    const float* b03 = (const float*)d_in[12];
    float* out = (float*)d_out;

    const int B = in_sizes[0] / DK;

    prep_weights_kernel<<<(NI * DK * HN + 255) / 256, 256>>>(W1, W2);
    prep_bias_kernel<<<(NI * 208 + 255) / 256, 256>>>(b1, b2, W3, b3);
    prep_dim0_kernel<<<1, 64>>>(w01, b01, w02, b02, w03, b03);

    static bool attr_set = false;
    if (!attr_set) {
        cudaFuncSetAttribute(mlplist_main_kernel,
                             cudaFuncAttributeMaxDynamicSharedMemorySize, SMEM_BYTES);
        attr_set = true;
    }
    const int pairs = (B + 255) / 256;
    dim3 grid(pairs, NI);
    mlplist_main_kernel<<<grid, 128, SMEM_BYTES>>>(x, out, B);
}

// round 6
// speedup vs baseline: 1.3501x; 1.3501x over previous
#include <cuda_runtime.h>
#include <cuda_bf16.h>
#include <cstdint>

// ============================================================================
// MLPList: B=32768 rows, 63 stacked MLPs (64->64->64->1), causal input mask.
// R6: R4 loop structure (X staged once per CTA, i-loop over 63 MLPs) but
// single-buffered weights with split cp.async commit groups (W1 waited before
// layer1, W2 waited before layer2 under layer-1 MMA cover) -> 66KB smem ->
// 3 CTAs/SM = 3 independent phase streams per SMSP.
// ============================================================================
#define NI 63
#define DK 64
#define HN 64

__device__ __align__(16) unsigned char g_wpack[NI * 32768]; // W1hi,W1lo,W2hi,W2lo (8KB each)
__device__ __align__(16) float g_bpack[NI * 208];           // b1[64], b2[64], w3[64], b3, pad
__device__ float g_o0;

// ---------------------------------------------------------------------------
__device__ __forceinline__ uint32_t smem_u32(const void* p) {
    uint32_t a;
    asm("{ .reg .u64 t; cvta.to.shared.u64 t, %1; cvt.u32.u64 %0, t; }"
        : "=r"(a) : "l"(p));
    return a;
}

__device__ __forceinline__ void split2(float a, float b, uint32_t& hi, uint32_t& lo) {
    __nv_bfloat16 ha = __float2bfloat16(a), hb = __float2bfloat16(b);
    float ra = a - __bfloat162float(ha);
    float rb = b - __bfloat162float(hb);
    __nv_bfloat16 la = __float2bfloat16(ra), lb = __float2bfloat16(rb);
    hi = ((uint32_t)__bfloat16_as_ushort(hb) << 16) | (uint32_t)__bfloat16_as_ushort(ha);
    lo = ((uint32_t)__bfloat16_as_ushort(lb) << 16) | (uint32_t)__bfloat16_as_ushort(la);
}

__device__ __forceinline__ void mma16816(float* d, const uint32_t* a, const uint32_t* b) {
    asm volatile(
        "mma.sync.aligned.m16n8k16.row.col.f32.bf16.bf16.f32 "
        "{%0,%1,%2,%3}, {%4,%5,%6,%7}, {%8,%9}, {%0,%1,%2,%3};"
        : "+f"(d[0]), "+f"(d[1]), "+f"(d[2]), "+f"(d[3])
        : "r"(a[0]), "r"(a[1]), "r"(a[2]), "r"(a[3]), "r"(b[0]), "r"(b[1]));
}

// ============================================================================
// Prep kernels
// ============================================================================
__global__ void prep_weights_kernel(const float* __restrict__ W1,
                                    const float* __restrict__ W2) {
    int idx = blockIdx.x * blockDim.x + threadIdx.x;
    if (idx >= NI * DK * HN) return;
    int i = idx >> 12;
    int n = (idx >> 6) & 63;
    int k = idx & 63;
    uint32_t off = (uint32_t)(n * 128) + (uint32_t)((k * 2) ^ ((n & 7) << 4));
    unsigned char* base = g_wpack + (size_t)i * 32768;

    float v1 = (k <= i) ? W1[((size_t)i * DK + k) * HN + n] : 0.0f;
    __nv_bfloat16 h1 = __float2bfloat16(v1);
    __nv_bfloat16 l1 = __float2bfloat16(v1 - __bfloat162float(h1));
    *(__nv_bfloat16*)(base + 0 * 8192 + off) = h1;
    *(__nv_bfloat16*)(base + 1 * 8192 + off) = l1;

    float v2 = W2[((size_t)i * HN + k) * HN + n];
    __nv_bfloat16 h2 = __float2bfloat16(v2);
    __nv_bfloat16 l2 = __float2bfloat16(v2 - __bfloat162float(h2));
    *(__nv_bfloat16*)(base + 2 * 8192 + off) = h2;
    *(__nv_bfloat16*)(base + 3 * 8192 + off) = l2;
}

__global__ void prep_bias_kernel(const float* __restrict__ b1, const float* __restrict__ b2,
                                 const float* __restrict__ W3, const float* __restrict__ b3) {
    int idx = blockIdx.x * blockDim.x + threadIdx.x;
    if (idx >= NI * 208) return;
    int i = idx / 208, t = idx % 208;
    float v = 0.0f;
    if (t < 64)       v = b1[i * 64 + t];
    else if (t < 128) v = b2[i * 64 + (t - 64)];
    else if (t < 192) v = W3[i * 64 + (t - 128)];
    else if (t == 192) v = b3[i];
    g_bpack[i * 208 + t] = v;
}

__global__ void prep_dim0_kernel(const float* __restrict__ w01, const float* __restrict__ b01,
                                 const float* __restrict__ w02, const float* __restrict__ b02,
                                 const float* __restrict__ w03, const float* __restrict__ b03) {
    __shared__ float h0s[64];
    __shared__ float ps[64];
    int h = threadIdx.x;
    float a = b01[h];
#pragma unroll
    for (int t = 0; t < 10; t++) {
        float v = 0.1f * (-5.0f + (float)t * (10.0f / 9.0f));
        a = fmaf(v, w01[t * 64 + h], a);
    }
    h0s[h] = fmaxf(a, 0.0f);
    __syncthreads();
    float a2 = b02[h];
#pragma unroll
    for (int k = 0; k < 64; k++) a2 = fmaf(h0s[k], w02[k * 64 + h], a2);
    ps[h] = fmaxf(a2, 0.0f) * w03[h];
    __syncthreads();
    if (h == 0) {
        float s = b03[0];
        for (int k = 0; k < 64; k++) s += ps[k];
        g_o0 = s;
    }
}

// ============================================================================
// Main kernel
// ============================================================================
constexpr int OFF_XHI  = 0;              // 128x64 bf16 hi tile (16KB, swizzled)
constexpr int OFF_XLO  = 16384;          // lo tile
constexpr int OFF_W    = 32768;          // single buffer: W1hi,W1lo,W2hi,W2lo (8KB each)
constexpr int OFF_BIAS = 65536;          // 832B
constexpr int SMEM_BYTES = 66432;

__global__ void __launch_bounds__(128, 3)
mlplist_main_kernel(const float* __restrict__ x, float* __restrict__ out, int B) {
    extern __shared__ char smem[];
    const int tid  = threadIdx.x;
    const int warp = tid >> 5, lane = tid & 31;
    const int tig  = lane & 3, grp = lane >> 2;
    const uint32_t sw = (uint32_t)grp << 4;
    const int rowBase = blockIdx.x * 128;
    const float o0 = g_o0;

    const char*  Wb   = smem + OFF_W;
    const float* bias = (const float*)(smem + OFF_BIAS);
    const uint32_t wdst = smem_u32(smem + OFF_W);

    // ---- load & split X tile once (thread = row) ----
    {
        const int row = rowBase + tid;
        if (row < B) {
            const float4* xr = (const float4*)(x + (size_t)row * DK);
#pragma unroll
            for (int c = 0; c < 8; c++) {
                float4 f0 = xr[2 * c], f1 = xr[2 * c + 1];
                uint4 hp, lp;
                split2(f0.x, f0.y, hp.x, lp.x);
                split2(f0.z, f0.w, hp.y, lp.y);
                split2(f1.x, f1.y, hp.z, lp.z);
                split2(f1.z, f1.w, hp.w, lp.w);
                uint32_t off = (uint32_t)(tid * 128) + (uint32_t)((c * 16) ^ ((tid & 7) << 4));
                *(uint4*)(smem + OFF_XHI + off) = hp;
                *(uint4*)(smem + OFF_XLO + off) = lp;
            }
        }
    }

    for (int i = 0; i < NI; i++) {
        __syncthreads();   // all reads of W/bias from prior iteration complete

        // ---- stage W1+bias (group A) then W2 (group B) ----
        {
            const unsigned char* src = g_wpack + (size_t)i * 32768;
#pragma unroll
            for (int j = 0; j < 8; j++) {       // W1hi+W1lo = 16KB
                int c = tid + j * 128;
                asm volatile("cp.async.cg.shared.global [%0], [%1], 16;"
                             :: "r"(wdst + c * 16), "l"(src + (size_t)c * 16));
            }
            if (tid < 52) {
                const float* bsrc = g_bpack + (size_t)i * 208;
                asm volatile("cp.async.cg.shared.global [%0], [%1], 16;"
                             :: "r"(smem_u32(smem + OFF_BIAS) + tid * 16),
                                "l"((const char*)bsrc + tid * 16));
            }
            asm volatile("cp.async.commit_group;" ::: "memory");
#pragma unroll
            for (int j = 8; j < 16; j++) {      // W2hi+W2lo = 16KB
                int c = tid + j * 128;
                asm volatile("cp.async.cg.shared.global [%0], [%1], 16;"
                             :: "r"(wdst + c * 16), "l"(src + (size_t)c * 16));
            }
            asm volatile("cp.async.commit_group;" ::: "memory");
        }
        asm volatile("cp.async.wait_group 1;" ::: "memory");  // W1+bias landed
        __syncthreads();

        const float* b1v = bias, * b2v = bias + 64, * w3v = bias + 128;
        const float  b3v = bias[192];

        float acc[2][8][4];
#pragma unroll
        for (int m = 0; m < 2; m++)
#pragma unroll
            for (int j = 0; j < 8; j++)
#pragma unroll
                for (int r = 0; r < 4; r++) acc[m][j][r] = 0.0f;

        // ---- Layer 1: acc += Xsplit @ W1split^T (masked K chunks skipped) ----
        const int kt1 = (i >> 4) + 1;
        for (int kt = 0; kt < kt1; kt++) {
            const uint32_t k0 = (uint32_t)(kt * 32 + tig * 4);
            uint32_t aH[2][4], aL[2][4];
#pragma unroll
            for (int m = 0; m < 2; m++) {
                const int r0 = warp * 32 + m * 16 + grp, r1 = r0 + 8;
                const uint32_t o00 = r0 * 128 + (k0 ^ sw);
                const uint32_t o10 = r1 * 128 + (k0 ^ sw);
                const uint32_t o01 = r0 * 128 + ((k0 + 16) ^ sw);
                const uint32_t o11 = r1 * 128 + ((k0 + 16) ^ sw);
                aH[m][0] = *(const uint32_t*)(smem + OFF_XHI + o00);
                aH[m][1] = *(const uint32_t*)(smem + OFF_XHI + o10);
                aH[m][2] = *(const uint32_t*)(smem + OFF_XHI + o01);
                aH[m][3] = *(const uint32_t*)(smem + OFF_XHI + o11);
                aL[m][0] = *(const uint32_t*)(smem + OFF_XLO + o00);
                aL[m][1] = *(const uint32_t*)(smem + OFF_XLO + o10);
                aL[m][2] = *(const uint32_t*)(smem + OFF_XLO + o01);
                aL[m][3] = *(const uint32_t*)(smem + OFF_XLO + o11);
            }
#pragma unroll
            for (int g = 0; g < 2; g++) {
                uint32_t bH[4][2], bL[4][2];
#pragma unroll
                for (int jj = 0; jj < 4; jj++) {
                    const int n = (g * 4 + jj) * 8 + grp;
                    const uint32_t ob0 = n * 128 + (k0 ^ sw);
                    const uint32_t ob1 = n * 128 + ((k0 + 16) ^ sw);
                    bH[jj][0] = *(const uint32_t*)(Wb + 0 * 8192 + ob0);
                    bH[jj][1] = *(const uint32_t*)(Wb + 0 * 8192 + ob1);
                    bL[jj][0] = *(const uint32_t*)(Wb + 1 * 8192 + ob0);
                    bL[jj][1] = *(const uint32_t*)(Wb + 1 * 8192 + ob1);
                }
#pragma unroll
                for (int jj = 0; jj < 4; jj++) {
                    const int j = g * 4 + jj;
                    mma16816(acc[0][j], aH[0], bH[jj]);
                    mma16816(acc[1][j], aH[1], bH[jj]);
                }
#pragma unroll
                for (int jj = 0; jj < 4; jj++) {
                    const int j = g * 4 + jj;
                    mma16816(acc[0][j], aH[0], bL[jj]);
                    mma16816(acc[1][j], aH[1], bL[jj]);
                }
#pragma unroll
                for (int jj = 0; jj < 4; jj++) {
                    const int j = g * 4 + jj;
                    mma16816(acc[0][j], aL[0], bH[jj]);
                    mma16816(acc[1][j], aL[1], bH[jj]);
                }
            }
        }

        // ---- bias + relu + split -> layer-2 A fragments (registers only) ----
        uint32_t A2H[2][4][4], A2L[2][4][4];
#pragma unroll
        for (int m = 0; m < 2; m++)
#pragma unroll
            for (int k2 = 0; k2 < 4; k2++) {
                const int j0 = 2 * k2, j1 = 2 * k2 + 1;
                const int c0 = j0 * 8 + 2 * tig;
                const int c1 = j1 * 8 + 2 * tig;
                const float bb00 = b1v[c0], bb01 = b1v[c0 + 1];
                const float bb10 = b1v[c1], bb11 = b1v[c1 + 1];
                float v00 = fmaxf(acc[m][j0][0] + bb00, 0.f);
                float v01 = fmaxf(acc[m][j0][1] + bb01, 0.f);
                float v02 = fmaxf(acc[m][j0][2] + bb00, 0.f);
                float v03 = fmaxf(acc[m][j0][3] + bb01, 0.f);
                float v10 = fmaxf(acc[m][j1][0] + bb10, 0.f);
                float v11 = fmaxf(acc[m][j1][1] + bb11, 0.f);
                float v12 = fmaxf(acc[m][j1][2] + bb10, 0.f);
                float v13 = fmaxf(acc[m][j1][3] + bb11, 0.f);
                split2(v00, v01, A2H[m][k2][0], A2L[m][k2][0]);
                split2(v02, v03, A2H[m][k2][1], A2L[m][k2][1]);
                split2(v10, v11, A2H[m][k2][2], A2L[m][k2][2]);
                split2(v12, v13, A2H[m][k2][3], A2L[m][k2][3]);
            }

        // ---- wait for W2 (hidden under layer-1 MMAs) ----
        asm volatile("cp.async.wait_group 0;" ::: "memory");
        __syncthreads();

        // ---- Layer 2 ----
#pragma unroll
        for (int m = 0; m < 2; m++)
#pragma unroll
            for (int j = 0; j < 8; j++)
#pragma unroll
                for (int r = 0; r < 4; r++) acc[m][j][r] = 0.0f;

#pragma unroll
        for (int k2 = 0; k2 < 4; k2++) {
            const uint32_t k0 = (uint32_t)(k2 * 32 + tig * 4);
#pragma unroll
            for (int g = 0; g < 2; g++) {
                uint32_t bH[4][2], bL[4][2];
#pragma unroll
                for (int jj = 0; jj < 4; jj++) {
                    const int n = (g * 4 + jj) * 8 + grp;
                    const uint32_t ob0 = n * 128 + (k0 ^ sw);
                    const uint32_t ob1 = n * 128 + ((k0 + 16) ^ sw);
                    bH[jj][0] = *(const uint32_t*)(Wb + 2 * 8192 + ob0);
                    bH[jj][1] = *(const uint32_t*)(Wb + 2 * 8192 + ob1);
                    bL[jj][0] = *(const uint32_t*)(Wb + 3 * 8192 + ob0);
                    bL[jj][1] = *(const uint32_t*)(Wb + 3 * 8192 + ob1);
                }
#pragma unroll
                for (int jj = 0; jj < 4; jj++) {
                    const int j = g * 4 + jj;
                    mma16816(acc[0][j], A2H[0][k2], bH[jj]);
                    mma16816(acc[1][j], A2H[1][k2], bH[jj]);
                }
#pragma unroll
                for (int jj = 0; jj < 4; jj++) {
                    const int j = g * 4 + jj;
                    mma16816(acc[0][j], A2H[0][k2], bL[jj]);
                    mma16816(acc[1][j], A2H[1][k2], bL[jj]);
                }
#pragma unroll
                for (int jj = 0; jj < 4; jj++) {
                    const int j = g * 4 + jj;
                    mma16816(acc[0][j], A2L[0][k2], bH[jj]);
                    mma16816(acc[1][j], A2L[1][k2], bH[jj]);
                }
            }
        }

        // ---- Layer 3: bias + relu + dot(w3) + quad reduce + store ----
#pragma unroll
        for (int m = 0; m < 2; m++) {
            float p0 = 0.f, p1 = 0.f;
#pragma unroll
            for (int j = 0; j < 8; j++) {
                const int c = 8 * j + 2 * tig;
                const float w0 = w3v[c], w1 = w3v[c + 1];
                const float bb0 = b2v[c], bb1 = b2v[c + 1];
                p0 += fmaxf(acc[m][j][0] + bb0, 0.f) * w0
                    + fmaxf(acc[m][j][1] + bb1, 0.f) * w1;
                p1 += fmaxf(acc[m][j][2] + bb0, 0.f) * w0
                    + fmaxf(acc[m][j][3] + bb1, 0.f) * w1;
            }
            p0 += __shfl_xor_sync(0xFFFFFFFFu, p0, 1);
            p0 += __shfl_xor_sync(0xFFFFFFFFu, p0, 2);
            p1 += __shfl_xor_sync(0xFFFFFFFFu, p1, 1);
            p1 += __shfl_xor_sync(0xFFFFFFFFu, p1, 2);
            if (tig == 0) {
                const int row = rowBase + warp * 32 + m * 16 + grp;
                if (row < B)     out[(size_t)row * 64 + (i + 1)]       = p0 + b3v;
                if (row + 8 < B) out[(size_t)(row + 8) * 64 + (i + 1)] = p1 + b3v;
            }
        }
    }

    if (rowBase + tid < B) out[(size_t)(rowBase + tid) * 64] = o0;
}

// ============================================================================
// Launch
// ============================================================================
extern "C" void kernel_launch(void* const* d_in, const int* in_sizes, int n_in,
                              void* d_out, int out_size) {
    const float* x   = (const float*)d_in[0];
    const float* W1  = (const float*)d_in[1];
    const float* b1  = (const float*)d_in[2];
    const float* W2  = (const float*)d_in[3];
    const float* b2  = (const float*)d_in[4];
    const float* W3  = (const float*)d_in[5];
    const float* b3  = (const float*)d_in[6];
    const float* w01 = (const float*)d_in[7];
    const float* b01 = (const float*)d_in[8];
    const float* w02 = (const float*)d_in[9];
    const float* b02 = (const float*)d_in[10];
    const float* w03 = (const float*)d_in[11];
    const float* b03 = (const float*)d_in[12];
    float* out = (float*)d_out;

    const int B = in_sizes[0] / DK;

    prep_weights_kernel<<<(NI * DK * HN + 255) / 256, 256>>>(W1, W2);
    prep_bias_kernel<<<(NI * 208 + 255) / 256, 256>>>(b1, b2, W3, b3);
    prep_dim0_kernel<<<1, 64>>>(w01, b01, w02, b02, w03, b03);

    static bool attr_set = false;
    if (!attr_set) {
        cudaFuncSetAttribute(mlplist_main_kernel,
                             cudaFuncAttributeMaxDynamicSharedMemorySize, SMEM_BYTES);
        attr_set = true;
    }
    const int grid = (B + 127) / 128;
    mlplist_main_kernel<<<grid, 128, SMEM_BYTES>>>(x, out, B);
}

// round 7
// speedup vs baseline: 1.4027x; 1.0389x over previous
#include <cuda_runtime.h>
#include <cuda_bf16.h>
#include <cstdint>

// ============================================================================
// MLPList: B=32768 rows, 63 stacked MLPs (64->64->64->1), causal input mask.
// R7 = R4 (best) + phase-stagger: CTAs with blockIdx >= 148 process i in
// DESCENDING order so co-resident CTA pairs (b, b+148) are never in the same
// phase (variable kt1 keeps them decorrelated). Breaks the MMA/epilogue
// phase lock that capped tensor pipe at 55%.
// ============================================================================
#define NI 63
#define DK 64
#define HN 64

__device__ __align__(16) unsigned char g_wpack[NI * 32768];
__device__ __align__(16) float g_bpack[NI * 208];   // b1[64], b2[64], w3[64], b3, pad
__device__ float g_o0;

// ---------------------------------------------------------------------------
__device__ __forceinline__ uint32_t smem_u32(const void* p) {
    uint32_t a;
    asm("{ .reg .u64 t; cvta.to.shared.u64 t, %1; cvt.u32.u64 %0, t; }"
        : "=r"(a) : "l"(p));
    return a;
}

__device__ __forceinline__ void split2(float a, float b, uint32_t& hi, uint32_t& lo) {
    __nv_bfloat16 ha = __float2bfloat16(a), hb = __float2bfloat16(b);
    float ra = a - __bfloat162float(ha);
    float rb = b - __bfloat162float(hb);
    __nv_bfloat16 la = __float2bfloat16(ra), lb = __float2bfloat16(rb);
    hi = ((uint32_t)__bfloat16_as_ushort(hb) << 16) | (uint32_t)__bfloat16_as_ushort(ha);
    lo = ((uint32_t)__bfloat16_as_ushort(lb) << 16) | (uint32_t)__bfloat16_as_ushort(la);
}

__device__ __forceinline__ void mma16816(float* d, const uint32_t* a, const uint32_t* b) {
    asm volatile(
        "mma.sync.aligned.m16n8k16.row.col.f32.bf16.bf16.f32 "
        "{%0,%1,%2,%3}, {%4,%5,%6,%7}, {%8,%9}, {%0,%1,%2,%3};"
        : "+f"(d[0]), "+f"(d[1]), "+f"(d[2]), "+f"(d[3])
        : "r"(a[0]), "r"(a[1]), "r"(a[2]), "r"(a[3]), "r"(b[0]), "r"(b[1]));
}

// ============================================================================
// Prep kernels
// ============================================================================
__global__ void prep_weights_kernel(const float* __restrict__ W1,
                                    const float* __restrict__ W2) {
    int idx = blockIdx.x * blockDim.x + threadIdx.x;
    if (idx >= NI * DK * HN) return;
    int i = idx >> 12;
    int n = (idx >> 6) & 63;
    int k = idx & 63;
    uint32_t off = (uint32_t)(n * 128) + (uint32_t)((k * 2) ^ ((n & 7) << 4));
    unsigned char* base = g_wpack + (size_t)i * 32768;

    float v1 = (k <= i) ? W1[((size_t)i * DK + k) * HN + n] : 0.0f;
    __nv_bfloat16 h1 = __float2bfloat16(v1);
    __nv_bfloat16 l1 = __float2bfloat16(v1 - __bfloat162float(h1));
    *(__nv_bfloat16*)(base + 0 * 8192 + off) = h1;
    *(__nv_bfloat16*)(base + 1 * 8192 + off) = l1;

    float v2 = W2[((size_t)i * HN + k) * HN + n];
    __nv_bfloat16 h2 = __float2bfloat16(v2);
    __nv_bfloat16 l2 = __float2bfloat16(v2 - __bfloat162float(h2));
    *(__nv_bfloat16*)(base + 2 * 8192 + off) = h2;
    *(__nv_bfloat16*)(base + 3 * 8192 + off) = l2;
}

__global__ void prep_bias_kernel(const float* __restrict__ b1, const float* __restrict__ b2,
                                 const float* __restrict__ W3, const float* __restrict__ b3) {
    int idx = blockIdx.x * blockDim.x + threadIdx.x;
    if (idx >= NI * 208) return;
    int i = idx / 208, t = idx % 208;
    float v = 0.0f;
    if (t < 64)       v = b1[i * 64 + t];
    else if (t < 128) v = b2[i * 64 + (t - 64)];
    else if (t < 192) v = W3[i * 64 + (t - 128)];
    else if (t == 192) v = b3[i];
    g_bpack[i * 208 + t] = v;
}

__global__ void prep_dim0_kernel(const float* __restrict__ w01, const float* __restrict__ b01,
                                 const float* __restrict__ w02, const float* __restrict__ b02,
                                 const float* __restrict__ w03, const float* __restrict__ b03) {
    __shared__ float h0s[64];
    __shared__ float ps[64];
    int h = threadIdx.x;
    float a = b01[h];
#pragma unroll
    for (int t = 0; t < 10; t++) {
        float v = 0.1f * (-5.0f + (float)t * (10.0f / 9.0f));
        a = fmaf(v, w01[t * 64 + h], a);
    }
    h0s[h] = fmaxf(a, 0.0f);
    __syncthreads();
    float a2 = b02[h];
#pragma unroll
    for (int k = 0; k < 64; k++) a2 = fmaf(h0s[k], w02[k * 64 + h], a2);
    ps[h] = fmaxf(a2, 0.0f) * w03[h];
    __syncthreads();
    if (h == 0) {
        float s = b03[0];
        for (int k = 0; k < 64; k++) s += ps[k];
        g_o0 = s;
    }
}

// ============================================================================
// Main kernel
// ============================================================================
constexpr int OFF_XHI  = 0;
constexpr int OFF_XLO  = 16384;
constexpr int OFF_W    = 32768;          // 2 x 32768B (W1hi,W1lo,W2hi,W2lo)
constexpr int OFF_BIAS = 98304;          // 2 x 832B
constexpr int SMEM_BYTES = 99968;

__device__ __forceinline__ void stage_i(char* smem, int i, int buf, int tid) {
    const unsigned char* src = g_wpack + (size_t)i * 32768;
    uint32_t dst = smem_u32(smem + OFF_W + buf * 32768);
#pragma unroll
    for (int j = 0; j < 16; j++) {
        int c = tid + j * 128;
        asm volatile("cp.async.cg.shared.global [%0], [%1], 16;"
                     :: "r"(dst + c * 16), "l"(src + (size_t)c * 16));
    }
    if (tid < 52) {
        const float* bsrc = g_bpack + (size_t)i * 208;
        uint32_t bdst = smem_u32(smem + OFF_BIAS + buf * 832) + tid * 16;
        asm volatile("cp.async.cg.shared.global [%0], [%1], 16;"
                     :: "r"(bdst), "l"((const char*)bsrc + tid * 16));
    }
    asm volatile("cp.async.commit_group;" ::: "memory");
}

__global__ void __launch_bounds__(128, 2)
mlplist_main_kernel(const float* __restrict__ x, float* __restrict__ out, int B) {
    extern __shared__ char smem[];
    const int tid  = threadIdx.x;
    const int warp = tid >> 5, lane = tid & 31;
    const int tig  = lane & 3, grp = lane >> 2;
    const uint32_t sw = (uint32_t)grp << 4;
    const int rowBase = blockIdx.x * 128;
    const float o0 = g_o0;

    // Phase stagger: co-resident CTA pairs (b, b+148) run opposite i orders.
    const bool desc = (blockIdx.x >= 148);

    // ---- load & split X tile (thread = row) ----
    {
        const int row = rowBase + tid;
        if (row < B) {
            const float4* xr = (const float4*)(x + (size_t)row * DK);
#pragma unroll
            for (int c = 0; c < 8; c++) {
                float4 f0 = xr[2 * c], f1 = xr[2 * c + 1];
                uint4 hp, lp;
                split2(f0.x, f0.y, hp.x, lp.x);
                split2(f0.z, f0.w, hp.y, lp.y);
                split2(f1.x, f1.y, hp.z, lp.z);
                split2(f1.z, f1.w, hp.w, lp.w);
                uint32_t off = (uint32_t)(tid * 128) + (uint32_t)((c * 16) ^ ((tid & 7) << 4));
                *(uint4*)(smem + OFF_XHI + off) = hp;
                *(uint4*)(smem + OFF_XLO + off) = lp;
            }
        }
    }

    stage_i(smem, desc ? (NI - 1) : 0, 0, tid);

    for (int t = 0; t < NI; t++) {
        const int i = desc ? (NI - 1 - t) : t;
        const int buf = t & 1;
        __syncthreads();
        if (t + 1 < NI) {
            const int inext = desc ? (NI - 2 - t) : (t + 1);
            stage_i(smem, inext, buf ^ 1, tid);
            asm volatile("cp.async.wait_group 1;" ::: "memory");
        } else {
            asm volatile("cp.async.wait_group 0;" ::: "memory");
        }
        __syncthreads();

        const char*  Wb   = smem + OFF_W + buf * 32768;
        const float* bias = (const float*)(smem + OFF_BIAS + buf * 832);
        const float* b1v = bias, * b2v = bias + 64, * w3v = bias + 128;
        const float  b3v = bias[192];

        float acc[2][8][4];
#pragma unroll
        for (int m = 0; m < 2; m++)
#pragma unroll
            for (int j = 0; j < 8; j++)
#pragma unroll
                for (int r = 0; r < 4; r++) acc[m][j][r] = 0.0f;

        // ---- Layer 1 (product-major MMA order) ----
        const int kt1 = (i >> 4) + 1;
        for (int kt = 0; kt < kt1; kt++) {
            const uint32_t k0 = (uint32_t)(kt * 32 + tig * 4);
            uint32_t aH[2][4], aL[2][4];
#pragma unroll
            for (int m = 0; m < 2; m++) {
                const int r0 = warp * 32 + m * 16 + grp, r1 = r0 + 8;
                const uint32_t o00 = r0 * 128 + (k0 ^ sw);
                const uint32_t o10 = r1 * 128 + (k0 ^ sw);
                const uint32_t o01 = r0 * 128 + ((k0 + 16) ^ sw);
                const uint32_t o11 = r1 * 128 + ((k0 + 16) ^ sw);
                aH[m][0] = *(const uint32_t*)(smem + OFF_XHI + o00);
                aH[m][1] = *(const uint32_t*)(smem + OFF_XHI + o10);
                aH[m][2] = *(const uint32_t*)(smem + OFF_XHI + o01);
                aH[m][3] = *(const uint32_t*)(smem + OFF_XHI + o11);
                aL[m][0] = *(const uint32_t*)(smem + OFF_XLO + o00);
                aL[m][1] = *(const uint32_t*)(smem + OFF_XLO + o10);
                aL[m][2] = *(const uint32_t*)(smem + OFF_XLO + o01);
                aL[m][3] = *(const uint32_t*)(smem + OFF_XLO + o11);
            }
            uint32_t bH[8][2], bL[8][2];
#pragma unroll
            for (int j = 0; j < 8; j++) {
                const int n = j * 8 + grp;
                const uint32_t ob0 = n * 128 + (k0 ^ sw);
                const uint32_t ob1 = n * 128 + ((k0 + 16) ^ sw);
                bH[j][0] = *(const uint32_t*)(Wb + 0 * 8192 + ob0);
                bH[j][1] = *(const uint32_t*)(Wb + 0 * 8192 + ob1);
                bL[j][0] = *(const uint32_t*)(Wb + 1 * 8192 + ob0);
                bL[j][1] = *(const uint32_t*)(Wb + 1 * 8192 + ob1);
            }
#pragma unroll
            for (int j = 0; j < 8; j++) {
                mma16816(acc[0][j], aH[0], bH[j]);
                mma16816(acc[1][j], aH[1], bH[j]);
            }
#pragma unroll
            for (int j = 0; j < 8; j++) {
                mma16816(acc[0][j], aH[0], bL[j]);
                mma16816(acc[1][j], aH[1], bL[j]);
            }
#pragma unroll
            for (int j = 0; j < 8; j++) {
                mma16816(acc[0][j], aL[0], bH[j]);
                mma16816(acc[1][j], aL[1], bH[j]);
            }
        }

        // ---- bias + relu + split -> layer-2 A fragments (registers only) ----
        uint32_t A2H[2][4][4], A2L[2][4][4];
#pragma unroll
        for (int m = 0; m < 2; m++)
#pragma unroll
            for (int k2 = 0; k2 < 4; k2++) {
                const int j0 = 2 * k2, j1 = 2 * k2 + 1;
                const int c0 = j0 * 8 + 2 * tig;
                const int c1 = j1 * 8 + 2 * tig;
                const float bb00 = b1v[c0], bb01 = b1v[c0 + 1];
                const float bb10 = b1v[c1], bb11 = b1v[c1 + 1];
                float v00 = fmaxf(acc[m][j0][0] + bb00, 0.f);
                float v01 = fmaxf(acc[m][j0][1] + bb01, 0.f);
                float v02 = fmaxf(acc[m][j0][2] + bb00, 0.f);
                float v03 = fmaxf(acc[m][j0][3] + bb01, 0.f);
                float v10 = fmaxf(acc[m][j1][0] + bb10, 0.f);
                float v11 = fmaxf(acc[m][j1][1] + bb11, 0.f);
                float v12 = fmaxf(acc[m][j1][2] + bb10, 0.f);
                float v13 = fmaxf(acc[m][j1][3] + bb11, 0.f);
                split2(v00, v01, A2H[m][k2][0], A2L[m][k2][0]);
                split2(v02, v03, A2H[m][k2][1], A2L[m][k2][1]);
                split2(v10, v11, A2H[m][k2][2], A2L[m][k2][2]);
                split2(v12, v13, A2H[m][k2][3], A2L[m][k2][3]);
            }

        // ---- Layer 2 ----
#pragma unroll
        for (int m = 0; m < 2; m++)
#pragma unroll
            for (int j = 0; j < 8; j++)
#pragma unroll
                for (int r = 0; r < 4; r++) acc[m][j][r] = 0.0f;

#pragma unroll
        for (int k2 = 0; k2 < 4; k2++) {
            const uint32_t k0 = (uint32_t)(k2 * 32 + tig * 4);
            uint32_t bH[8][2], bL[8][2];
#pragma unroll
            for (int j = 0; j < 8; j++) {
                const int n = j * 8 + grp;
                const uint32_t ob0 = n * 128 + (k0 ^ sw);
                const uint32_t ob1 = n * 128 + ((k0 + 16) ^ sw);
                bH[j][0] = *(const uint32_t*)(Wb + 2 * 8192 + ob0);
                bH[j][1] = *(const uint32_t*)(Wb + 2 * 8192 + ob1);
                bL[j][0] = *(const uint32_t*)(Wb + 3 * 8192 + ob0);
                bL[j][1] = *(const uint32_t*)(Wb + 3 * 8192 + ob1);
            }
#pragma unroll
            for (int j = 0; j < 8; j++) {
                mma16816(acc[0][j], A2H[0][k2], bH[j]);
                mma16816(acc[1][j], A2H[1][k2], bH[j]);
            }
#pragma unroll
            for (int j = 0; j < 8; j++) {
                mma16816(acc[0][j], A2H[0][k2], bL[j]);
                mma16816(acc[1][j], A2H[1][k2], bL[j]);
            }
#pragma unroll
            for (int j = 0; j < 8; j++) {
                mma16816(acc[0][j], A2L[0][k2], bH[j]);
                mma16816(acc[1][j], A2L[1][k2], bH[j]);
            }
        }

        // ---- Layer 3: bias + relu + dot(w3) + quad reduce + store ----
#pragma unroll
        for (int m = 0; m < 2; m++) {
            float p0 = 0.f, p1 = 0.f;
#pragma unroll
            for (int j = 0; j < 8; j++) {
                const int c = 8 * j + 2 * tig;
                const float w0 = w3v[c], w1 = w3v[c + 1];
                const float bb0 = b2v[c], bb1 = b2v[c + 1];
                p0 += fmaxf(acc[m][j][0] + bb0, 0.f) * w0
                    + fmaxf(acc[m][j][1] + bb1, 0.f) * w1;
                p1 += fmaxf(acc[m][j][2] + bb0, 0.f) * w0
                    + fmaxf(acc[m][j][3] + bb1, 0.f) * w1;
            }
            p0 += __shfl_xor_sync(0xFFFFFFFFu, p0, 1);
            p0 += __shfl_xor_sync(0xFFFFFFFFu, p0, 2);
            p1 += __shfl_xor_sync(0xFFFFFFFFu, p1, 1);
            p1 += __shfl_xor_sync(0xFFFFFFFFu, p1, 2);
            if (tig == 0) {
                const int row = rowBase + warp * 32 + m * 16 + grp;
                if (row < B)     out[(size_t)row * 64 + (i + 1)]       = p0 + b3v;
                if (row + 8 < B) out[(size_t)(row + 8) * 64 + (i + 1)] = p1 + b3v;
            }
        }
    }

    if (rowBase + tid < B) out[(size_t)(rowBase + tid) * 64] = o0;
}

// ============================================================================
// Launch
// ============================================================================
extern "C" void kernel_launch(void* const* d_in, const int* in_sizes, int n_in,
                              void* d_out, int out_size) {
    const float* x   = (const float*)d_in[0];
    const float* W1  = (const float*)d_in[1];
    const float* b1  = (const float*)d_in[2];
    const float* W2  = (const float*)d_in[3];
    const float* b2  = (const float*)d_in[4];
    const float* W3  = (const float*)d_in[5];
    const float* b3  = (const float*)d_in[6];
    const float* w01 = (const float*)d_in[7];
    const float* b01 = (const float*)d_in[8];
    const float* w02 = (const float*)d_in[9];
    const float* b02 = (const float*)d_in[10];
    const float* w03 = (const float*)d_in[11];
    const float* b03 = (const float*)d_in[12];
    float* out = (float*)d_out;

    const int B = in_sizes[0] / DK;

    prep_weights_kernel<<<(NI * DK * HN + 255) / 256, 256>>>(W1, W2);
    prep_bias_kernel<<<(NI * 208 + 255) / 256, 256>>>(b1, b2, W3, b3);
    prep_dim0_kernel<<<1, 64>>>(w01, b01, w02, b02, w03, b03);

    static bool attr_set = false;
    if (!attr_set) {
        cudaFuncSetAttribute(mlplist_main_kernel,
                             cudaFuncAttributeMaxDynamicSharedMemorySize, SMEM_BYTES);
        attr_set = true;
    }
    const int grid = (B + 127) / 128;
    mlplist_main_kernel<<<grid, 128, SMEM_BYTES>>>(x, out, B);
}

// round 8
// speedup vs baseline: 1.9696x; 1.4042x over previous
#include <cuda_runtime.h>
#include <cuda_fp16.h>
#include <cstdint>

// ============================================================================
// MLPList: B=32768 rows, 63 stacked MLPs (64->64->64->1), causal input mask.
// R8 = R4 structure + asymmetric fp16 scheme: activations single fp16,
// weights fp16 hi+lo => 2 MMAs per logical product (was 3 bf16 MMAs).
// Error budget: ~2^-12 per layer from A rounding => ~3e-4 total (< 1e-3).
// ============================================================================
#define NI 63
#define DK 64
#define HN 64

__device__ __align__(16) unsigned char g_wpack[NI * 32768]; // W1hi,W1lo,W2hi,W2lo (8KB each, fp16)
__device__ __align__(16) float g_bpack[NI * 208];           // b1[64], b2[64], w3[64], b3, pad
__device__ float g_o0;

// ---------------------------------------------------------------------------
__device__ __forceinline__ uint32_t smem_u32(const void* p) {
    uint32_t a;
    asm("{ .reg .u64 t; cvta.to.shared.u64 t, %1; cvt.u32.u64 %0, t; }"
        : "=r"(a) : "l"(p));
    return a;
}

// pack two floats into one fp16x2 register
__device__ __forceinline__ uint32_t packh2(float a, float b) {
    __half2 h = __floats2half2_rn(a, b);
    return *(uint32_t*)&h;
}

// fp16 m16n8k16 row.col MMA, fp32 accumulate
__device__ __forceinline__ void mma16816(float* d, const uint32_t* a, const uint32_t* b) {
    asm volatile(
        "mma.sync.aligned.m16n8k16.row.col.f32.f16.f16.f32 "
        "{%0,%1,%2,%3}, {%4,%5,%6,%7}, {%8,%9}, {%0,%1,%2,%3};"
        : "+f"(d[0]), "+f"(d[1]), "+f"(d[2]), "+f"(d[3])
        : "r"(a[0]), "r"(a[1]), "r"(a[2]), "r"(a[3]), "r"(b[0]), "r"(b[1]));
}

// ============================================================================
// Prep kernels
// ============================================================================
// Weight image: element (n,k) at byte n*128 + ((k*2) ^ ((n&7)<<4)); fp16 hi/lo.
__global__ void prep_weights_kernel(const float* __restrict__ W1,
                                    const float* __restrict__ W2) {
    int idx = blockIdx.x * blockDim.x + threadIdx.x;
    if (idx >= NI * DK * HN) return;
    int i = idx >> 12;
    int n = (idx >> 6) & 63;
    int k = idx & 63;
    uint32_t off = (uint32_t)(n * 128) + (uint32_t)((k * 2) ^ ((n & 7) << 4));
    unsigned char* base = g_wpack + (size_t)i * 32768;

    float v1 = (k <= i) ? W1[((size_t)i * DK + k) * HN + n] : 0.0f;
    __half h1 = __float2half_rn(v1);
    __half l1 = __float2half_rn(v1 - __half2float(h1));
    *(__half*)(base + 0 * 8192 + off) = h1;
    *(__half*)(base + 1 * 8192 + off) = l1;

    float v2 = W2[((size_t)i * HN + k) * HN + n];
    __half h2 = __float2half_rn(v2);
    __half l2 = __float2half_rn(v2 - __half2float(h2));
    *(__half*)(base + 2 * 8192 + off) = h2;
    *(__half*)(base + 3 * 8192 + off) = l2;
}

__global__ void prep_bias_kernel(const float* __restrict__ b1, const float* __restrict__ b2,
                                 const float* __restrict__ W3, const float* __restrict__ b3) {
    int idx = blockIdx.x * blockDim.x + threadIdx.x;
    if (idx >= NI * 208) return;
    int i = idx / 208, t = idx % 208;
    float v = 0.0f;
    if (t < 64)       v = b1[i * 64 + t];
    else if (t < 128) v = b2[i * 64 + (t - 64)];
    else if (t < 192) v = W3[i * 64 + (t - 128)];
    else if (t == 192) v = b3[i];
    g_bpack[i * 208 + t] = v;
}

__global__ void prep_dim0_kernel(const float* __restrict__ w01, const float* __restrict__ b01,
                                 const float* __restrict__ w02, const float* __restrict__ b02,
                                 const float* __restrict__ w03, const float* __restrict__ b03) {
    __shared__ float h0s[64];
    __shared__ float ps[64];
    int h = threadIdx.x;
    float a = b01[h];
#pragma unroll
    for (int t = 0; t < 10; t++) {
        float v = 0.1f * (-5.0f + (float)t * (10.0f / 9.0f));
        a = fmaf(v, w01[t * 64 + h], a);
    }
    h0s[h] = fmaxf(a, 0.0f);
    __syncthreads();
    float a2 = b02[h];
#pragma unroll
    for (int k = 0; k < 64; k++) a2 = fmaf(h0s[k], w02[k * 64 + h], a2);
    ps[h] = fmaxf(a2, 0.0f) * w03[h];
    __syncthreads();
    if (h == 0) {
        float s = b03[0];
        for (int k = 0; k < 64; k++) s += ps[k];
        g_o0 = s;
    }
}

// ============================================================================
// Main kernel
// ============================================================================
constexpr int OFF_X    = 0;              // 128x64 fp16 X tile (16KB, swizzled)
constexpr int OFF_W    = 16384;          // 2 x 32768B (W1hi,W1lo,W2hi,W2lo)
constexpr int OFF_BIAS = 81920;          // 2 x 832B
constexpr int SMEM_BYTES = 83584;

__device__ __forceinline__ void stage_i(char* smem, int i, int buf, int tid) {
    const unsigned char* src = g_wpack + (size_t)i * 32768;
    uint32_t dst = smem_u32(smem + OFF_W + buf * 32768);
#pragma unroll
    for (int j = 0; j < 16; j++) {
        int c = tid + j * 128;
        asm volatile("cp.async.cg.shared.global [%0], [%1], 16;"
                     :: "r"(dst + c * 16), "l"(src + (size_t)c * 16));
    }
    if (tid < 52) {
        const float* bsrc = g_bpack + (size_t)i * 208;
        uint32_t bdst = smem_u32(smem + OFF_BIAS + buf * 832) + tid * 16;
        asm volatile("cp.async.cg.shared.global [%0], [%1], 16;"
                     :: "r"(bdst), "l"((const char*)bsrc + tid * 16));
    }
    asm volatile("cp.async.commit_group;" ::: "memory");
}

__global__ void __launch_bounds__(128, 2)
mlplist_main_kernel(const float* __restrict__ x, float* __restrict__ out, int B) {
    extern __shared__ char smem[];
    const int tid  = threadIdx.x;
    const int warp = tid >> 5, lane = tid & 31;
    const int tig  = lane & 3, grp = lane >> 2;
    const uint32_t sw = (uint32_t)grp << 4;
    const int rowBase = blockIdx.x * 128;
    const float o0 = g_o0;

    // ---- load X tile -> single fp16 swizzled tile (thread = row) ----
    {
        const int row = rowBase + tid;
        if (row < B) {
            const float4* xr = (const float4*)(x + (size_t)row * DK);
#pragma unroll
            for (int c = 0; c < 8; c++) {
                float4 f0 = xr[2 * c], f1 = xr[2 * c + 1];
                uint4 hp;
                hp.x = packh2(f0.x, f0.y);
                hp.y = packh2(f0.z, f0.w);
                hp.z = packh2(f1.x, f1.y);
                hp.w = packh2(f1.z, f1.w);
                uint32_t off = (uint32_t)(tid * 128) + (uint32_t)((c * 16) ^ ((tid & 7) << 4));
                *(uint4*)(smem + OFF_X + off) = hp;
            }
        }
    }

    stage_i(smem, 0, 0, tid);

    for (int i = 0; i < NI; i++) {
        const int buf = i & 1;
        __syncthreads();
        if (i + 1 < NI) {
            stage_i(smem, i + 1, buf ^ 1, tid);
            asm volatile("cp.async.wait_group 1;" ::: "memory");
        } else {
            asm volatile("cp.async.wait_group 0;" ::: "memory");
        }
        __syncthreads();

        const char*  Wb   = smem + OFF_W + buf * 32768;
        const float* bias = (const float*)(smem + OFF_BIAS + buf * 832);
        const float* b1v = bias, * b2v = bias + 64, * w3v = bias + 128;
        const float  b3v = bias[192];

        float acc[2][8][4];
#pragma unroll
        for (int m = 0; m < 2; m++)
#pragma unroll
            for (int j = 0; j < 8; j++)
#pragma unroll
                for (int r = 0; r < 4; r++) acc[m][j][r] = 0.0f;

        // ---- Layer 1: acc += X_fp16 @ (W1hi + W1lo)^T (masked K skipped) ----
        const int kt1 = (i >> 4) + 1;
        for (int kt = 0; kt < kt1; kt++) {
            const uint32_t k0 = (uint32_t)(kt * 32 + tig * 4);
            uint32_t aF[2][4];
#pragma unroll
            for (int m = 0; m < 2; m++) {
                const int r0 = warp * 32 + m * 16 + grp, r1 = r0 + 8;
                aF[m][0] = *(const uint32_t*)(smem + OFF_X + r0 * 128 + (k0 ^ sw));
                aF[m][1] = *(const uint32_t*)(smem + OFF_X + r1 * 128 + (k0 ^ sw));
                aF[m][2] = *(const uint32_t*)(smem + OFF_X + r0 * 128 + ((k0 + 16) ^ sw));
                aF[m][3] = *(const uint32_t*)(smem + OFF_X + r1 * 128 + ((k0 + 16) ^ sw));
            }
            uint32_t bH[8][2], bL[8][2];
#pragma unroll
            for (int j = 0; j < 8; j++) {
                const int n = j * 8 + grp;
                const uint32_t ob0 = n * 128 + (k0 ^ sw);
                const uint32_t ob1 = n * 128 + ((k0 + 16) ^ sw);
                bH[j][0] = *(const uint32_t*)(Wb + 0 * 8192 + ob0);
                bH[j][1] = *(const uint32_t*)(Wb + 0 * 8192 + ob1);
                bL[j][0] = *(const uint32_t*)(Wb + 1 * 8192 + ob0);
                bL[j][1] = *(const uint32_t*)(Wb + 1 * 8192 + ob1);
            }
#pragma unroll
            for (int j = 0; j < 8; j++) {
                mma16816(acc[0][j], aF[0], bH[j]);
                mma16816(acc[1][j], aF[1], bH[j]);
            }
#pragma unroll
            for (int j = 0; j < 8; j++) {
                mma16816(acc[0][j], aF[0], bL[j]);
                mma16816(acc[1][j], aF[1], bL[j]);
            }
        }

        // ---- bias + relu -> single fp16 layer-2 A fragments (registers) ----
        uint32_t A2[2][4][4];
#pragma unroll
        for (int m = 0; m < 2; m++)
#pragma unroll
            for (int k2 = 0; k2 < 4; k2++) {
                const int j0 = 2 * k2, j1 = 2 * k2 + 1;
                const int c0 = j0 * 8 + 2 * tig;
                const int c1 = j1 * 8 + 2 * tig;
                const float bb00 = b1v[c0], bb01 = b1v[c0 + 1];
                const float bb10 = b1v[c1], bb11 = b1v[c1 + 1];
                A2[m][k2][0] = packh2(fmaxf(acc[m][j0][0] + bb00, 0.f),
                                      fmaxf(acc[m][j0][1] + bb01, 0.f));
                A2[m][k2][1] = packh2(fmaxf(acc[m][j0][2] + bb00, 0.f),
                                      fmaxf(acc[m][j0][3] + bb01, 0.f));
                A2[m][k2][2] = packh2(fmaxf(acc[m][j1][0] + bb10, 0.f),
                                      fmaxf(acc[m][j1][1] + bb11, 0.f));
                A2[m][k2][3] = packh2(fmaxf(acc[m][j1][2] + bb10, 0.f),
                                      fmaxf(acc[m][j1][3] + bb11, 0.f));
            }

        // ---- Layer 2 ----
#pragma unroll
        for (int m = 0; m < 2; m++)
#pragma unroll
            for (int j = 0; j < 8; j++)
#pragma unroll
                for (int r = 0; r < 4; r++) acc[m][j][r] = 0.0f;

#pragma unroll
        for (int k2 = 0; k2 < 4; k2++) {
            const uint32_t k0 = (uint32_t)(k2 * 32 + tig * 4);
            uint32_t bH[8][2], bL[8][2];
#pragma unroll
            for (int j = 0; j < 8; j++) {
                const int n = j * 8 + grp;
                const uint32_t ob0 = n * 128 + (k0 ^ sw);
                const uint32_t ob1 = n * 128 + ((k0 + 16) ^ sw);
                bH[j][0] = *(const uint32_t*)(Wb + 2 * 8192 + ob0);
                bH[j][1] = *(const uint32_t*)(Wb + 2 * 8192 + ob1);
                bL[j][0] = *(const uint32_t*)(Wb + 3 * 8192 + ob0);
                bL[j][1] = *(const uint32_t*)(Wb + 3 * 8192 + ob1);
            }
#pragma unroll
            for (int j = 0; j < 8; j++) {
                mma16816(acc[0][j], A2[0][k2], bH[j]);
                mma16816(acc[1][j], A2[1][k2], bH[j]);
            }
#pragma unroll
            for (int j = 0; j < 8; j++) {
                mma16816(acc[0][j], A2[0][k2], bL[j]);
                mma16816(acc[1][j], A2[1][k2], bL[j]);
            }
        }

        // ---- Layer 3: bias + relu + dot(w3) + quad reduce + store ----
#pragma unroll
        for (int m = 0; m < 2; m++) {
            float p0 = 0.f, p1 = 0.f;
#pragma unroll
            for (int j = 0; j < 8; j++) {
                const int c = 8 * j + 2 * tig;
                const float w0 = w3v[c], w1 = w3v[c + 1];
                const float bb0 = b2v[c], bb1 = b2v[c + 1];
                p0 += fmaxf(acc[m][j][0] + bb0, 0.f) * w0
                    + fmaxf(acc[m][j][1] + bb1, 0.f) * w1;
                p1 += fmaxf(acc[m][j][2] + bb0, 0.f) * w0
                    + fmaxf(acc[m][j][3] + bb1, 0.f) * w1;
            }
            p0 += __shfl_xor_sync(0xFFFFFFFFu, p0, 1);
            p0 += __shfl_xor_sync(0xFFFFFFFFu, p0, 2);
            p1 += __shfl_xor_sync(0xFFFFFFFFu, p1, 1);
            p1 += __shfl_xor_sync(0xFFFFFFFFu, p1, 2);
            if (tig == 0) {
                const int row = rowBase + warp * 32 + m * 16 + grp;
                if (row < B)     out[(size_t)row * 64 + (i + 1)]       = p0 + b3v;
                if (row + 8 < B) out[(size_t)(row + 8) * 64 + (i + 1)] = p1 + b3v;
            }
        }
    }

    if (rowBase + tid < B) out[(size_t)(rowBase + tid) * 64] = o0;
}

// ============================================================================
// Launch
// ============================================================================
extern "C" void kernel_launch(void* const* d_in, const int* in_sizes, int n_in,
                              void* d_out, int out_size) {
    const float* x   = (const float*)d_in[0];
    const float* W1  = (const float*)d_in[1];
    const float* b1  = (const float*)d_in[2];
    const float* W2  = (const float*)d_in[3];
    const float* b2  = (const float*)d_in[4];
    const float* W3  = (const float*)d_in[5];
    const float* b3  = (const float*)d_in[6];
    const float* w01 = (const float*)d_in[7];
    const float* b01 = (const float*)d_in[8];
    const float* w02 = (const float*)d_in[9];
    const float* b02 = (const float*)d_in[10];
    const float* w03 = (const float*)d_in[11];
    const float* b03 = (const float*)d_in[12];
    float* out = (float*)d_out;

    const int B = in_sizes[0] / DK;

    prep_weights_kernel<<<(NI * DK * HN + 255) / 256, 256>>>(W1, W2);
    prep_bias_kernel<<<(NI * 208 + 255) / 256, 256>>>(b1, b2, W3, b3);
    prep_dim0_kernel<<<1, 64>>>(w01, b01, w02, b02, w03, b03);

    static bool attr_set = false;
    if (!attr_set) {
        cudaFuncSetAttribute(mlplist_main_kernel,
                             cudaFuncAttributeMaxDynamicSharedMemorySize, SMEM_BYTES);
        attr_set = true;
    }
    const int grid = (B + 127) / 128;
    mlplist_main_kernel<<<grid, 128, SMEM_BYTES>>>(x, out, B);
}

// round 9
// speedup vs baseline: 2.9804x; 1.5133x over previous
#include <cuda_runtime.h>
#include <cuda_fp16.h>
#include <cstdint>

// ============================================================================
// MLPList: B=32768 rows, 63 stacked MLPs (64->64->64->1), causal input mask.
// R9 = R8 structure + single-fp16 weights: activations fp16, weights fp16
// (no hi/lo correction) => 1 MMA per logical product. Error: A-rounding
// (measured 1.13e-4 in R8) + similar independent W-rounding => ~2e-4 < 1e-3.
// ============================================================================
#define NI 63
#define DK 64
#define HN 64

__device__ __align__(16) unsigned char g_wpack[NI * 16384]; // W1,W2 fp16 (8KB each)
__device__ __align__(16) float g_bpack[NI * 208];           // b1[64], b2[64], w3[64], b3, pad
__device__ float g_o0;

// ---------------------------------------------------------------------------
__device__ __forceinline__ uint32_t smem_u32(const void* p) {
    uint32_t a;
    asm("{ .reg .u64 t; cvta.to.shared.u64 t, %1; cvt.u32.u64 %0, t; }"
        : "=r"(a) : "l"(p));
    return a;
}

__device__ __forceinline__ uint32_t packh2(float a, float b) {
    __half2 h = __floats2half2_rn(a, b);
    return *(uint32_t*)&h;
}

__device__ __forceinline__ void mma16816(float* d, const uint32_t* a, const uint32_t* b) {
    asm volatile(
        "mma.sync.aligned.m16n8k16.row.col.f32.f16.f16.f32 "
        "{%0,%1,%2,%3}, {%4,%5,%6,%7}, {%8,%9}, {%0,%1,%2,%3};"
        : "+f"(d[0]), "+f"(d[1]), "+f"(d[2]), "+f"(d[3])
        : "r"(a[0]), "r"(a[1]), "r"(a[2]), "r"(a[3]), "r"(b[0]), "r"(b[1]));
}

// ============================================================================
// Prep kernels
// ============================================================================
// Weight image per i: 16KB = W1 (8KB) + W2 (8KB), fp16, element (n,k) at
// byte n*128 + ((k*2) ^ ((n&7)<<4)).
__global__ void prep_weights_kernel(const float* __restrict__ W1,
                                    const float* __restrict__ W2) {
    int idx = blockIdx.x * blockDim.x + threadIdx.x;
    if (idx >= NI * DK * HN) return;
    int i = idx >> 12;
    int n = (idx >> 6) & 63;
    int k = idx & 63;
    uint32_t off = (uint32_t)(n * 128) + (uint32_t)((k * 2) ^ ((n & 7) << 4));
    unsigned char* base = g_wpack + (size_t)i * 16384;

    float v1 = (k <= i) ? W1[((size_t)i * DK + k) * HN + n] : 0.0f;
    *(__half*)(base + 0 * 8192 + off) = __float2half_rn(v1);

    float v2 = W2[((size_t)i * HN + k) * HN + n];
    *(__half*)(base + 1 * 8192 + off) = __float2half_rn(v2);
}

__global__ void prep_bias_kernel(const float* __restrict__ b1, const float* __restrict__ b2,
                                 const float* __restrict__ W3, const float* __restrict__ b3) {
    int idx = blockIdx.x * blockDim.x + threadIdx.x;
    if (idx >= NI * 208) return;
    int i = idx / 208, t = idx % 208;
    float v = 0.0f;
    if (t < 64)       v = b1[i * 64 + t];
    else if (t < 128) v = b2[i * 64 + (t - 64)];
    else if (t < 192) v = W3[i * 64 + (t - 128)];
    else if (t == 192) v = b3[i];
    g_bpack[i * 208 + t] = v;
}

__global__ void prep_dim0_kernel(const float* __restrict__ w01, const float* __restrict__ b01,
                                 const float* __restrict__ w02, const float* __restrict__ b02,
                                 const float* __restrict__ w03, const float* __restrict__ b03) {
    __shared__ float h0s[64];
    __shared__ float ps[64];
    int h = threadIdx.x;
    float a = b01[h];
#pragma unroll
    for (int t = 0; t < 10; t++) {
        float v = 0.1f * (-5.0f + (float)t * (10.0f / 9.0f));
        a = fmaf(v, w01[t * 64 + h], a);
    }
    h0s[h] = fmaxf(a, 0.0f);
    __syncthreads();
    float a2 = b02[h];
#pragma unroll
    for (int k = 0; k < 64; k++) a2 = fmaf(h0s[k], w02[k * 64 + h], a2);
    ps[h] = fmaxf(a2, 0.0f) * w03[h];
    __syncthreads();
    if (h == 0) {
        float s = b03[0];
        for (int k = 0; k < 64; k++) s += ps[k];
        g_o0 = s;
    }
}

// ============================================================================
// Main kernel
// ============================================================================
constexpr int OFF_X    = 0;              // 128x64 fp16 X tile (16KB, swizzled)
constexpr int OFF_W    = 16384;          // 2 x 16384B (W1, W2)
constexpr int OFF_BIAS = 49152;          // 2 x 832B
constexpr int SMEM_BYTES = 50816;

__device__ __forceinline__ void stage_i(char* smem, int i, int buf, int tid) {
    const unsigned char* src = g_wpack + (size_t)i * 16384;
    uint32_t dst = smem_u32(smem + OFF_W + buf * 16384);
#pragma unroll
    for (int j = 0; j < 8; j++) {
        int c = tid + j * 128;   // 1024 chunks of 16B = 16KB
        asm volatile("cp.async.cg.shared.global [%0], [%1], 16;"
                     :: "r"(dst + c * 16), "l"(src + (size_t)c * 16));
    }
    if (tid < 52) {
        const float* bsrc = g_bpack + (size_t)i * 208;
        uint32_t bdst = smem_u32(smem + OFF_BIAS + buf * 832) + tid * 16;
        asm volatile("cp.async.cg.shared.global [%0], [%1], 16;"
                     :: "r"(bdst), "l"((const char*)bsrc + tid * 16));
    }
    asm volatile("cp.async.commit_group;" ::: "memory");
}

__global__ void __launch_bounds__(128, 2)
mlplist_main_kernel(const float* __restrict__ x, float* __restrict__ out, int B) {
    extern __shared__ char smem[];
    const int tid  = threadIdx.x;
    const int warp = tid >> 5, lane = tid & 31;
    const int tig  = lane & 3, grp = lane >> 2;
    const uint32_t sw = (uint32_t)grp << 4;
    const int rowBase = blockIdx.x * 128;
    const float o0 = g_o0;

    // ---- load X tile -> fp16 swizzled tile (thread = row) ----
    {
        const int row = rowBase + tid;
        if (row < B) {
            const float4* xr = (const float4*)(x + (size_t)row * DK);
#pragma unroll
            for (int c = 0; c < 8; c++) {
                float4 f0 = xr[2 * c], f1 = xr[2 * c + 1];
                uint4 hp;
                hp.x = packh2(f0.x, f0.y);
                hp.y = packh2(f0.z, f0.w);
                hp.z = packh2(f1.x, f1.y);
                hp.w = packh2(f1.z, f1.w);
                uint32_t off = (uint32_t)(tid * 128) + (uint32_t)((c * 16) ^ ((tid & 7) << 4));
                *(uint4*)(smem + OFF_X + off) = hp;
            }
        }
    }

    stage_i(smem, 0, 0, tid);

    for (int i = 0; i < NI; i++) {
        const int buf = i & 1;
        __syncthreads();
        if (i + 1 < NI) {
            stage_i(smem, i + 1, buf ^ 1, tid);
            asm volatile("cp.async.wait_group 1;" ::: "memory");
        } else {
            asm volatile("cp.async.wait_group 0;" ::: "memory");
        }
        __syncthreads();

        const char*  Wb   = smem + OFF_W + buf * 16384;
        const float* bias = (const float*)(smem + OFF_BIAS + buf * 832);
        const float* b1v = bias, * b2v = bias + 64, * w3v = bias + 128;
        const float  b3v = bias[192];

        float acc[2][8][4];
#pragma unroll
        for (int m = 0; m < 2; m++)
#pragma unroll
            for (int j = 0; j < 8; j++)
#pragma unroll
                for (int r = 0; r < 4; r++) acc[m][j][r] = 0.0f;

        // ---- Layer 1: acc += X_fp16 @ W1_fp16^T (masked K chunks skipped) ----
        const int kt1 = (i >> 4) + 1;
        for (int kt = 0; kt < kt1; kt++) {
            const uint32_t k0 = (uint32_t)(kt * 32 + tig * 4);
            uint32_t aF[2][4];
#pragma unroll
            for (int m = 0; m < 2; m++) {
                const int r0 = warp * 32 + m * 16 + grp, r1 = r0 + 8;
                aF[m][0] = *(const uint32_t*)(smem + OFF_X + r0 * 128 + (k0 ^ sw));
                aF[m][1] = *(const uint32_t*)(smem + OFF_X + r1 * 128 + (k0 ^ sw));
                aF[m][2] = *(const uint32_t*)(smem + OFF_X + r0 * 128 + ((k0 + 16) ^ sw));
                aF[m][3] = *(const uint32_t*)(smem + OFF_X + r1 * 128 + ((k0 + 16) ^ sw));
            }
            uint32_t bF[8][2];
#pragma unroll
            for (int j = 0; j < 8; j++) {
                const int n = j * 8 + grp;
                bF[j][0] = *(const uint32_t*)(Wb + 0 * 8192 + n * 128 + (k0 ^ sw));
                bF[j][1] = *(const uint32_t*)(Wb + 0 * 8192 + n * 128 + ((k0 + 16) ^ sw));
            }
#pragma unroll
            for (int j = 0; j < 8; j++) {
                mma16816(acc[0][j], aF[0], bF[j]);
                mma16816(acc[1][j], aF[1], bF[j]);
            }
        }

        // ---- bias + relu -> fp16 layer-2 A fragments (registers only) ----
        uint32_t A2[2][4][4];
#pragma unroll
        for (int m = 0; m < 2; m++)
#pragma unroll
            for (int k2 = 0; k2 < 4; k2++) {
                const int j0 = 2 * k2, j1 = 2 * k2 + 1;
                const int c0 = j0 * 8 + 2 * tig;
                const int c1 = j1 * 8 + 2 * tig;
                const float bb00 = b1v[c0], bb01 = b1v[c0 + 1];
                const float bb10 = b1v[c1], bb11 = b1v[c1 + 1];
                A2[m][k2][0] = packh2(fmaxf(acc[m][j0][0] + bb00, 0.f),
                                      fmaxf(acc[m][j0][1] + bb01, 0.f));
                A2[m][k2][1] = packh2(fmaxf(acc[m][j0][2] + bb00, 0.f),
                                      fmaxf(acc[m][j0][3] + bb01, 0.f));
                A2[m][k2][2] = packh2(fmaxf(acc[m][j1][0] + bb10, 0.f),
                                      fmaxf(acc[m][j1][1] + bb11, 0.f));
                A2[m][k2][3] = packh2(fmaxf(acc[m][j1][2] + bb10, 0.f),
                                      fmaxf(acc[m][j1][3] + bb11, 0.f));
            }

        // ---- Layer 2 ----
#pragma unroll
        for (int m = 0; m < 2; m++)
#pragma unroll
            for (int j = 0; j < 8; j++)
#pragma unroll
                for (int r = 0; r < 4; r++) acc[m][j][r] = 0.0f;

#pragma unroll
        for (int k2 = 0; k2 < 4; k2++) {
            const uint32_t k0 = (uint32_t)(k2 * 32 + tig * 4);
            uint32_t bF[8][2];
#pragma unroll
            for (int j = 0; j < 8; j++) {
                const int n = j * 8 + grp;
                bF[j][0] = *(const uint32_t*)(Wb + 1 * 8192 + n * 128 + (k0 ^ sw));
                bF[j][1] = *(const uint32_t*)(Wb + 1 * 8192 + n * 128 + ((k0 + 16) ^ sw));
            }
#pragma unroll
            for (int j = 0; j < 8; j++) {
                mma16816(acc[0][j], A2[0][k2], bF[j]);
                mma16816(acc[1][j], A2[1][k2], bF[j]);
            }
        }

        // ---- Layer 3: bias + relu + dot(w3) + quad reduce + store ----
#pragma unroll
        for (int m = 0; m < 2; m++) {
            float p0 = 0.f, p1 = 0.f;
#pragma unroll
            for (int j = 0; j < 8; j++) {
                const int c = 8 * j + 2 * tig;
                const float w0 = w3v[c], w1 = w3v[c + 1];
                const float bb0 = b2v[c], bb1 = b2v[c + 1];
                p0 += fmaxf(acc[m][j][0] + bb0, 0.f) * w0
                    + fmaxf(acc[m][j][1] + bb1, 0.f) * w1;
                p1 += fmaxf(acc[m][j][2] + bb0, 0.f) * w0
                    + fmaxf(acc[m][j][3] + bb1, 0.f) * w1;
            }
            p0 += __shfl_xor_sync(0xFFFFFFFFu, p0, 1);
            p0 += __shfl_xor_sync(0xFFFFFFFFu, p0, 2);
            p1 += __shfl_xor_sync(0xFFFFFFFFu, p1, 1);
            p1 += __shfl_xor_sync(0xFFFFFFFFu, p1, 2);
            if (tig == 0) {
                const int row = rowBase + warp * 32 + m * 16 + grp;
                if (row < B)     out[(size_t)row * 64 + (i + 1)]       = p0 + b3v;
                if (row + 8 < B) out[(size_t)(row + 8) * 64 + (i + 1)] = p1 + b3v;
            }
        }
    }

    if (rowBase + tid < B) out[(size_t)(rowBase + tid) * 64] = o0;
}

// ============================================================================
// Launch
// ============================================================================
extern "C" void kernel_launch(void* const* d_in, const int* in_sizes, int n_in,
                              void* d_out, int out_size) {
    const float* x   = (const float*)d_in[0];
    const float* W1  = (const float*)d_in[1];
    const float* b1  = (const float*)d_in[2];
    const float* W2  = (const float*)d_in[3];
    const float* b2  = (const float*)d_in[4];
    const float* W3  = (const float*)d_in[5];
    const float* b3  = (const float*)d_in[6];
    const float* w01 = (const float*)d_in[7];
    const float* b01 = (const float*)d_in[8];
    const float* w02 = (const float*)d_in[9];
    const float* b02 = (const float*)d_in[10];
    const float* w03 = (const float*)d_in[11];
    const float* b03 = (const float*)d_in[12];
    float* out = (float*)d_out;

    const int B = in_sizes[0] / DK;

    prep_weights_kernel<<<(NI * DK * HN + 255) / 256, 256>>>(W1, W2);
    prep_bias_kernel<<<(NI * 208 + 255) / 256, 256>>>(b1, b2, W3, b3);
    prep_dim0_kernel<<<1, 64>>>(w01, b01, w02, b02, w03, b03);

    static bool attr_set = false;
    if (!attr_set) {
        cudaFuncSetAttribute(mlplist_main_kernel,
                             cudaFuncAttributeMaxDynamicSharedMemorySize, SMEM_BYTES);
        attr_set = true;
    }
    const int grid = (B + 127) / 128;
    mlplist_main_kernel<<<grid, 128, SMEM_BYTES>>>(x, out, B);
}

// round 10
// speedup vs baseline: 3.3469x; 1.1229x over previous
#include <cuda_runtime.h>
#include <cuda_fp16.h>
#include <cstdint>

// ============================================================================
// MLPList: B=32768 rows, 63 stacked MLPs (64->64->64->1), causal input mask.
// R10 = R9 (fp16 1-MMA-per-product) + 4-way interleaved i-split:
// blockIdx.y = chunk, CTA processes i = chunk, chunk+4, ... Grid 1024,
// __launch_bounds__(128,3) -> 3 CTAs/SM = 12 warps to hide LDS->MMA latency.
// ============================================================================
#define NI 63
#define DK 64
#define HN 64
#define NCHUNK 4

__device__ __align__(16) unsigned char g_wpack[NI * 16384]; // W1,W2 fp16 (8KB each)
__device__ __align__(16) float g_bpack[NI * 208];           // b1[64], b2[64], w3[64], b3, pad
__device__ float g_o0;

// ---------------------------------------------------------------------------
__device__ __forceinline__ uint32_t smem_u32(const void* p) {
    uint32_t a;
    asm("{ .reg .u64 t; cvta.to.shared.u64 t, %1; cvt.u32.u64 %0, t; }"
        : "=r"(a) : "l"(p));
    return a;
}

__device__ __forceinline__ uint32_t packh2(float a, float b) {
    __half2 h = __floats2half2_rn(a, b);
    return *(uint32_t*)&h;
}

__device__ __forceinline__ void mma16816(float* d, const uint32_t* a, const uint32_t* b) {
    asm volatile(
        "mma.sync.aligned.m16n8k16.row.col.f32.f16.f16.f32 "
        "{%0,%1,%2,%3}, {%4,%5,%6,%7}, {%8,%9}, {%0,%1,%2,%3};"
        : "+f"(d[0]), "+f"(d[1]), "+f"(d[2]), "+f"(d[3])
        : "r"(a[0]), "r"(a[1]), "r"(a[2]), "r"(a[3]), "r"(b[0]), "r"(b[1]));
}

// ============================================================================
// Prep kernels
// ============================================================================
__global__ void prep_weights_kernel(const float* __restrict__ W1,
                                    const float* __restrict__ W2) {
    int idx = blockIdx.x * blockDim.x + threadIdx.x;
    if (idx >= NI * DK * HN) return;
    int i = idx >> 12;
    int n = (idx >> 6) & 63;
    int k = idx & 63;
    uint32_t off = (uint32_t)(n * 128) + (uint32_t)((k * 2) ^ ((n & 7) << 4));
    unsigned char* base = g_wpack + (size_t)i * 16384;

    float v1 = (k <= i) ? W1[((size_t)i * DK + k) * HN + n] : 0.0f;
    *(__half*)(base + 0 * 8192 + off) = __float2half_rn(v1);

    float v2 = W2[((size_t)i * HN + k) * HN + n];
    *(__half*)(base + 1 * 8192 + off) = __float2half_rn(v2);
}

__global__ void prep_bias_kernel(const float* __restrict__ b1, const float* __restrict__ b2,
                                 const float* __restrict__ W3, const float* __restrict__ b3) {
    int idx = blockIdx.x * blockDim.x + threadIdx.x;
    if (idx >= NI * 208) return;
    int i = idx / 208, t = idx % 208;
    float v = 0.0f;
    if (t < 64)       v = b1[i * 64 + t];
    else if (t < 128) v = b2[i * 64 + (t - 64)];
    else if (t < 192) v = W3[i * 64 + (t - 128)];
    else if (t == 192) v = b3[i];
    g_bpack[i * 208 + t] = v;
}

__global__ void prep_dim0_kernel(const float* __restrict__ w01, const float* __restrict__ b01,
                                 const float* __restrict__ w02, const float* __restrict__ b02,
                                 const float* __restrict__ w03, const float* __restrict__ b03) {
    __shared__ float h0s[64];
    __shared__ float ps[64];
    int h = threadIdx.x;
    float a = b01[h];
#pragma unroll
    for (int t = 0; t < 10; t++) {
        float v = 0.1f * (-5.0f + (float)t * (10.0f / 9.0f));
        a = fmaf(v, w01[t * 64 + h], a);
    }
    h0s[h] = fmaxf(a, 0.0f);
    __syncthreads();
    float a2 = b02[h];
#pragma unroll
    for (int k = 0; k < 64; k++) a2 = fmaf(h0s[k], w02[k * 64 + h], a2);
    ps[h] = fmaxf(a2, 0.0f) * w03[h];
    __syncthreads();
    if (h == 0) {
        float s = b03[0];
        for (int k = 0; k < 64; k++) s += ps[k];
        g_o0 = s;
    }
}

// ============================================================================
// Main kernel
// ============================================================================
constexpr int OFF_X    = 0;              // 128x64 fp16 X tile (16KB, swizzled)
constexpr int OFF_W    = 16384;          // 2 x 16384B (W1, W2)
constexpr int OFF_BIAS = 49152;          // 2 x 832B
constexpr int SMEM_BYTES = 50816;

__device__ __forceinline__ void stage_i(char* smem, int i, int buf, int tid) {
    const unsigned char* src = g_wpack + (size_t)i * 16384;
    uint32_t dst = smem_u32(smem + OFF_W + buf * 16384);
#pragma unroll
    for (int j = 0; j < 8; j++) {
        int c = tid + j * 128;   // 1024 chunks of 16B = 16KB
        asm volatile("cp.async.cg.shared.global [%0], [%1], 16;"
                     :: "r"(dst + c * 16), "l"(src + (size_t)c * 16));
    }
    if (tid < 52) {
        const float* bsrc = g_bpack + (size_t)i * 208;
        uint32_t bdst = smem_u32(smem + OFF_BIAS + buf * 832) + tid * 16;
        asm volatile("cp.async.cg.shared.global [%0], [%1], 16;"
                     :: "r"(bdst), "l"((const char*)bsrc + tid * 16));
    }
    asm volatile("cp.async.commit_group;" ::: "memory");
}

__global__ void __launch_bounds__(128, 3)
mlplist_main_kernel(const float* __restrict__ x, float* __restrict__ out, int B) {
    extern __shared__ char smem[];
    const int tid  = threadIdx.x;
    const int warp = tid >> 5, lane = tid & 31;
    const int tig  = lane & 3, grp = lane >> 2;
    const uint32_t sw = (uint32_t)grp << 4;
    const int rowBase = blockIdx.x * 128;
    const int chunk = blockIdx.y;
    const int niters = (NI - chunk + NCHUNK - 1) / NCHUNK;   // 16,16,16,15
    const float o0 = g_o0;

    // ---- load X tile -> fp16 swizzled tile (thread = row) ----
    {
        const int row = rowBase + tid;
        if (row < B) {
            const float4* xr = (const float4*)(x + (size_t)row * DK);
#pragma unroll
            for (int c = 0; c < 8; c++) {
                float4 f0 = xr[2 * c], f1 = xr[2 * c + 1];
                uint4 hp;
                hp.x = packh2(f0.x, f0.y);
                hp.y = packh2(f0.z, f0.w);
                hp.z = packh2(f1.x, f1.y);
                hp.w = packh2(f1.z, f1.w);
                uint32_t off = (uint32_t)(tid * 128) + (uint32_t)((c * 16) ^ ((tid & 7) << 4));
                *(uint4*)(smem + OFF_X + off) = hp;
            }
        }
    }

    stage_i(smem, chunk, 0, tid);

    for (int t = 0; t < niters; t++) {
        const int i = chunk + t * NCHUNK;
        const int buf = t & 1;
        __syncthreads();
        if (t + 1 < niters) {
            stage_i(smem, i + NCHUNK, buf ^ 1, tid);
            asm volatile("cp.async.wait_group 1;" ::: "memory");
        } else {
            asm volatile("cp.async.wait_group 0;" ::: "memory");
        }
        __syncthreads();

        const char*  Wb   = smem + OFF_W + buf * 16384;
        const float* bias = (const float*)(smem + OFF_BIAS + buf * 832);
        const float* b1v = bias, * b2v = bias + 64, * w3v = bias + 128;
        const float  b3v = bias[192];

        float acc[2][8][4];
#pragma unroll
        for (int m = 0; m < 2; m++)
#pragma unroll
            for (int j = 0; j < 8; j++)
#pragma unroll
                for (int r = 0; r < 4; r++) acc[m][j][r] = 0.0f;

        // ---- Layer 1: acc += X_fp16 @ W1_fp16^T (masked K chunks skipped) ----
        const int kt1 = (i >> 4) + 1;
        for (int kt = 0; kt < kt1; kt++) {
            const uint32_t k0 = (uint32_t)(kt * 32 + tig * 4);
            uint32_t aF[2][4];
#pragma unroll
            for (int m = 0; m < 2; m++) {
                const int r0 = warp * 32 + m * 16 + grp, r1 = r0 + 8;
                aF[m][0] = *(const uint32_t*)(smem + OFF_X + r0 * 128 + (k0 ^ sw));
                aF[m][1] = *(const uint32_t*)(smem + OFF_X + r1 * 128 + (k0 ^ sw));
                aF[m][2] = *(const uint32_t*)(smem + OFF_X + r0 * 128 + ((k0 + 16) ^ sw));
                aF[m][3] = *(const uint32_t*)(smem + OFF_X + r1 * 128 + ((k0 + 16) ^ sw));
            }
            uint32_t bF[8][2];
#pragma unroll
            for (int j = 0; j < 8; j++) {
                const int n = j * 8 + grp;
                bF[j][0] = *(const uint32_t*)(Wb + 0 * 8192 + n * 128 + (k0 ^ sw));
                bF[j][1] = *(const uint32_t*)(Wb + 0 * 8192 + n * 128 + ((k0 + 16) ^ sw));
            }
#pragma unroll
            for (int j = 0; j < 8; j++) {
                mma16816(acc[0][j], aF[0], bF[j]);
                mma16816(acc[1][j], aF[1], bF[j]);
            }
        }

        // ---- bias + relu -> fp16 layer-2 A fragments (registers only) ----
        uint32_t A2[2][4][4];
#pragma unroll
        for (int m = 0; m < 2; m++)
#pragma unroll
            for (int k2 = 0; k2 < 4; k2++) {
                const int j0 = 2 * k2, j1 = 2 * k2 + 1;
                const int c0 = j0 * 8 + 2 * tig;
                const int c1 = j1 * 8 + 2 * tig;
                const float bb00 = b1v[c0], bb01 = b1v[c0 + 1];
                const float bb10 = b1v[c1], bb11 = b1v[c1 + 1];
                A2[m][k2][0] = packh2(fmaxf(acc[m][j0][0] + bb00, 0.f),
                                      fmaxf(acc[m][j0][1] + bb01, 0.f));
                A2[m][k2][1] = packh2(fmaxf(acc[m][j0][2] + bb00, 0.f),
                                      fmaxf(acc[m][j0][3] + bb01, 0.f));
                A2[m][k2][2] = packh2(fmaxf(acc[m][j1][0] + bb10, 0.f),
                                      fmaxf(acc[m][j1][1] + bb11, 0.f));
                A2[m][k2][3] = packh2(fmaxf(acc[m][j1][2] + bb10, 0.f),
                                      fmaxf(acc[m][j1][3] + bb11, 0.f));
            }

        // ---- Layer 2 ----
#pragma unroll
        for (int m = 0; m < 2; m++)
#pragma unroll
            for (int j = 0; j < 8; j++)
#pragma unroll
                for (int r = 0; r < 4; r++) acc[m][j][r] = 0.0f;

#pragma unroll
        for (int k2 = 0; k2 < 4; k2++) {
            const uint32_t k0 = (uint32_t)(k2 * 32 + tig * 4);
            uint32_t bF[8][2];
#pragma unroll
            for (int j = 0; j < 8; j++) {
                const int n = j * 8 + grp;
                bF[j][0] = *(const uint32_t*)(Wb + 1 * 8192 + n * 128 + (k0 ^ sw));
                bF[j][1] = *(const uint32_t*)(Wb + 1 * 8192 + n * 128 + ((k0 + 16) ^ sw));
            }
#pragma unroll
            for (int j = 0; j < 8; j++) {
                mma16816(acc[0][j], A2[0][k2], bF[j]);
                mma16816(acc[1][j], A2[1][k2], bF[j]);
            }
        }

        // ---- Layer 3: bias + relu + dot(w3) + quad reduce + store ----
#pragma unroll
        for (int m = 0; m < 2; m++) {
            float p0 = 0.f, p1 = 0.f;
#pragma unroll
            for (int j = 0; j < 8; j++) {
                const int c = 8 * j + 2 * tig;
                const float w0 = w3v[c], w1 = w3v[c + 1];
                const float bb0 = b2v[c], bb1 = b2v[c + 1];
                p0 += fmaxf(acc[m][j][0] + bb0, 0.f) * w0
                    + fmaxf(acc[m][j][1] + bb1, 0.f) * w1;
                p1 += fmaxf(acc[m][j][2] + bb0, 0.f) * w0
                    + fmaxf(acc[m][j][3] + bb1, 0.f) * w1;
            }
            p0 += __shfl_xor_sync(0xFFFFFFFFu, p0, 1);
            p0 += __shfl_xor_sync(0xFFFFFFFFu, p0, 2);
            p1 += __shfl_xor_sync(0xFFFFFFFFu, p1, 1);
            p1 += __shfl_xor_sync(0xFFFFFFFFu, p1, 2);
            if (tig == 0) {
                const int row = rowBase + warp * 32 + m * 16 + grp;
                if (row < B)     out[(size_t)row * 64 + (i + 1)]       = p0 + b3v;
                if (row + 8 < B) out[(size_t)(row + 8) * 64 + (i + 1)] = p1 + b3v;
            }
        }
    }

    // dim-0 column (batch-constant), written by chunk-0 CTAs only
    if (chunk == 0 && rowBase + tid < B) out[(size_t)(rowBase + tid) * 64] = o0;
}

// ============================================================================
// Launch
// ============================================================================
extern "C" void kernel_launch(void* const* d_in, const int* in_sizes, int n_in,
                              void* d_out, int out_size) {
    const float* x   = (const float*)d_in[0];
    const float* W1  = (const float*)d_in[1];
    const float* b1  = (const float*)d_in[2];
    const float* W2  = (const float*)d_in[3];
    const float* b2  = (const float*)d_in[4];
    const float* W3  = (const float*)d_in[5];
    const float* b3  = (const float*)d_in[6];
    const float* w01 = (const float*)d_in[7];
    const float* b01 = (const float*)d_in[8];
    const float* w02 = (const float*)d_in[9];
    const float* b02 = (const float*)d_in[10];
    const float* w03 = (const float*)d_in[11];
    const float* b03 = (const float*)d_in[12];
    float* out = (float*)d_out;

    const int B = in_sizes[0] / DK;

    prep_weights_kernel<<<(NI * DK * HN + 255) / 256, 256>>>(W1, W2);
    prep_bias_kernel<<<(NI * 208 + 255) / 256, 256>>>(b1, b2, W3, b3);
    prep_dim0_kernel<<<1, 64>>>(w01, b01, w02, b02, w03, b03);

    static bool attr_set = false;
    if (!attr_set) {
        cudaFuncSetAttribute(mlplist_main_kernel,
                             cudaFuncAttributeMaxDynamicSharedMemorySize, SMEM_BYTES);
        attr_set = true;
    }
    dim3 grid((B + 127) / 128, NCHUNK);
    mlplist_main_kernel<<<grid, 128, SMEM_BYTES>>>(x, out, B);
}

// round 12
// speedup vs baseline: 3.4192x; 1.0216x over previous
#include <cuda_runtime.h>
#include <cuda_fp16.h>
#include <cstdint>

// ============================================================================
// MLPList: B=32768 rows, 63 stacked MLPs (64->64->64->1), causal input mask.
// R11 = R10 + ldmatrix.x4 fragment loads (1 LDSM replaces 4 LDS + addr math).
// fp16 single-precision-weights scheme (1 MMA/product), 4-way i-split grid,
// 3 CTAs/SM.
// ============================================================================
#define NI 63
#define DK 64
#define HN 64
#define NCHUNK 4

__device__ __align__(16) unsigned char g_wpack[NI * 16384]; // W1,W2 fp16 (8KB each)
__device__ __align__(16) float g_bpack[NI * 208];           // b1[64], b2[64], w3[64], b3, pad
__device__ float g_o0;

// ---------------------------------------------------------------------------
__device__ __forceinline__ uint32_t smem_u32(const void* p) {
    uint32_t a;
    asm("{ .reg .u64 t; cvta.to.shared.u64 t, %1; cvt.u32.u64 %0, t; }"
        : "=r"(a) : "l"(p));
    return a;
}

__device__ __forceinline__ uint32_t packh2(float a, float b) {
    __half2 h = __floats2half2_rn(a, b);
    return *(uint32_t*)&h;
}

__device__ __forceinline__ void mma16816(float* d, const uint32_t* a, const uint32_t* b) {
    asm volatile(
        "mma.sync.aligned.m16n8k16.row.col.f32.f16.f16.f32 "
        "{%0,%1,%2,%3}, {%4,%5,%6,%7}, {%8,%9}, {%0,%1,%2,%3};"
        : "+f"(d[0]), "+f"(d[1]), "+f"(d[2]), "+f"(d[3])
        : "r"(a[0]), "r"(a[1]), "r"(a[2]), "r"(a[3]), "r"(b[0]), "r"(b[1]));
}

__device__ __forceinline__ void ldsm4(uint32_t& r0, uint32_t& r1, uint32_t& r2,
                                      uint32_t& r3, uint32_t addr) {
    asm volatile("ldmatrix.sync.aligned.m8n8.x4.shared.b16 {%0,%1,%2,%3}, [%4];"
                 : "=r"(r0), "=r"(r1), "=r"(r2), "=r"(r3) : "r"(addr));
}

// ============================================================================
// Prep kernels
// ============================================================================
__global__ void prep_weights_kernel(const float* __restrict__ W1,
                                    const float* __restrict__ W2) {
    int idx = blockIdx.x * blockDim.x + threadIdx.x;
    if (idx >= NI * DK * HN) return;
    int i = idx >> 12;
    int n = (idx >> 6) & 63;
    int k = idx & 63;
    uint32_t off = (uint32_t)(n * 128) + (uint32_t)((k * 2) ^ ((n & 7) << 4));
    unsigned char* base = g_wpack + (size_t)i * 16384;

    float v1 = (k <= i) ? W1[((size_t)i * DK + k) * HN + n] : 0.0f;
    *(__half*)(base + 0 * 8192 + off) = __float2half_rn(v1);

    float v2 = W2[((size_t)i * HN + k) * HN + n];
    *(__half*)(base + 1 * 8192 + off) = __float2half_rn(v2);
}

__global__ void prep_bias_kernel(const float* __restrict__ b1, const float* __restrict__ b2,
                                 const float* __restrict__ W3, const float* __restrict__ b3) {
    int idx = blockIdx.x * blockDim.x + threadIdx.x;
    if (idx >= NI * 208) return;
    int i = idx / 208, t = idx % 208;
    float v = 0.0f;
    if (t < 64)       v = b1[i * 64 + t];
    else if (t < 128) v = b2[i * 64 + (t - 64)];
    else if (t < 192) v = W3[i * 64 + (t - 128)];
    else if (t == 192) v = b3[i];
    g_bpack[i * 208 + t] = v;
}

__global__ void prep_dim0_kernel(const float* __restrict__ w01, const float* __restrict__ b01,
                                 const float* __restrict__ w02, const float* __restrict__ b02,
                                 const float* __restrict__ w03, const float* __restrict__ b03) {
    __shared__ float h0s[64];
    __shared__ float ps[64];
    int h = threadIdx.x;
    float a = b01[h];
#pragma unroll
    for (int t = 0; t < 10; t++) {
        float v = 0.1f * (-5.0f + (float)t * (10.0f / 9.0f));
        a = fmaf(v, w01[t * 64 + h], a);
    }
    h0s[h] = fmaxf(a, 0.0f);
    __syncthreads();
    float a2 = b02[h];
#pragma unroll
    for (int k = 0; k < 64; k++) a2 = fmaf(h0s[k], w02[k * 64 + h], a2);
    ps[h] = fmaxf(a2, 0.0f) * w03[h];
    __syncthreads();
    if (h == 0) {
        float s = b03[0];
        for (int k = 0; k < 64; k++) s += ps[k];
        g_o0 = s;
    }
}

// ============================================================================
// Main kernel
// ============================================================================
constexpr int OFF_X    = 0;              // 128x64 fp16 X tile (16KB, swizzled)
constexpr int OFF_W    = 16384;          // 2 x 16384B (W1, W2)
constexpr int OFF_BIAS = 49152;          // 2 x 832B
constexpr int SMEM_BYTES = 50816;

__device__ __forceinline__ void stage_i(char* smem, int i, int buf, int tid) {
    const unsigned char* src = g_wpack + (size_t)i * 16384;
    uint32_t dst = smem_u32(smem + OFF_W + buf * 16384);
#pragma unroll
    for (int j = 0; j < 8; j++) {
        int c = tid + j * 128;   // 1024 chunks of 16B = 16KB
        asm volatile("cp.async.cg.shared.global [%0], [%1], 16;"
                     :: "r"(dst + c * 16), "l"(src + (size_t)c * 16));
    }
    if (tid < 52) {
        const float* bsrc = g_bpack + (size_t)i * 208;
        uint32_t bdst = smem_u32(smem + OFF_BIAS + buf * 832) + tid * 16;
        asm volatile("cp.async.cg.shared.global [%0], [%1], 16;"
                     :: "r"(bdst), "l"((const char*)bsrc + tid * 16));
    }
    asm volatile("cp.async.commit_group;" ::: "memory");
}

__global__ void __launch_bounds__(128, 3)
mlplist_main_kernel(const float* __restrict__ x, float* __restrict__ out, int B) {
    extern __shared__ char smem[];
    const int tid  = threadIdx.x;
    const int warp = tid >> 5, lane = tid & 31;
    const int tig  = lane & 3, grp = lane >> 2;
    const int q    = lane >> 3, r = lane & 7;    // ldmatrix lane decomposition
    const int rowBase = blockIdx.x * 128;
    const int chunk = blockIdx.y;
    const int niters = (NI - chunk + NCHUNK - 1) / NCHUNK;   // 16,16,16,15
    const float o0 = g_o0;

    // ---- ldmatrix per-lane address constants ----
    // A (X tile): matrix order a0(row,k0) a1(row+8,k0) a2(row,k8) a3(row+8,k8)
    //   lane q: row = R0 + (q&1)*8 + r, khalf = q>>1
    const uint32_t xbase = smem_u32(smem + OFF_X);
    uint32_t aBase[2];
#pragma unroll
    for (int m = 0; m < 2; m++) {
        const int arow = warp * 32 + m * 16 + (q & 1) * 8 + r;
        aBase[m] = xbase + (uint32_t)(arow * 128);
    }
    const uint32_t aLow = (uint32_t)(((q >> 1) * 16) ^ (r << 4));
    // B (W tiles): matrix order b[2g][0] b[2g][1] b[2g+1][0] b[2g+1][1]
    //   lane q: n = 16g + (q>>1)*8 + r, khalf = q&1
    uint32_t bRowOff[4];
#pragma unroll
    for (int g = 0; g < 4; g++)
        bRowOff[g] = (uint32_t)((16 * g + (q >> 1) * 8 + r) * 128);
    const uint32_t bLow = (uint32_t)(((q & 1) * 16) ^ (r << 4));

    // ---- load X tile -> fp16 swizzled tile (thread = row) ----
    {
        const int row = rowBase + tid;
        if (row < B) {
            const float4* xr = (const float4*)(x + (size_t)row * DK);
#pragma unroll
            for (int c = 0; c < 8; c++) {
                float4 f0 = xr[2 * c], f1 = xr[2 * c + 1];
                uint4 hp;
                hp.x = packh2(f0.x, f0.y);
                hp.y = packh2(f0.z, f0.w);
                hp.z = packh2(f1.x, f1.y);
                hp.w = packh2(f1.z, f1.w);
                uint32_t off = (uint32_t)(tid * 128) + (uint32_t)((c * 16) ^ ((tid & 7) << 4));
                *(uint4*)(smem + OFF_X + off) = hp;
            }
        }
    }

    stage_i(smem, chunk, 0, tid);

    for (int t = 0; t < niters; t++) {
        const int i = chunk + t * NCHUNK;
        const int buf = t & 1;
        __syncthreads();
        if (t + 1 < niters) {
            stage_i(smem, i + NCHUNK, buf ^ 1, tid);
            asm volatile("cp.async.wait_group 1;" ::: "memory");
        } else {
            asm volatile("cp.async.wait_group 0;" ::: "memory");
        }
        __syncthreads();

        const uint32_t wb1 = smem_u32(smem + OFF_W + buf * 16384);      // W1
        const uint32_t wb2 = wb1 + 8192;                                 // W2
        const float* bias = (const float*)(smem + OFF_BIAS + buf * 832);
        const float* b1v = bias, * b2v = bias + 64, * w3v = bias + 128;
        const float  b3v = bias[192];

        float acc[2][8][4];
#pragma unroll
        for (int m = 0; m < 2; m++)
#pragma unroll
            for (int j = 0; j < 8; j++)
#pragma unroll
                for (int rr = 0; rr < 4; rr++) acc[m][j][rr] = 0.0f;

        // ---- Layer 1: acc += X_fp16 @ W1_fp16^T (masked K chunks skipped) ----
        const int kt1 = (i >> 4) + 1;
        for (int kt = 0; kt < kt1; kt++) {
            const uint32_t kb = (uint32_t)(kt * 32);
            const uint32_t ao = aLow ^ kb;
            const uint32_t bo = bLow ^ kb;
            uint32_t aF[2][4];
            ldsm4(aF[0][0], aF[0][1], aF[0][2], aF[0][3], aBase[0] + ao);
            ldsm4(aF[1][0], aF[1][1], aF[1][2], aF[1][3], aBase[1] + ao);
            uint32_t bF[8][2];
#pragma unroll
            for (int g = 0; g < 4; g++)
                ldsm4(bF[2 * g][0], bF[2 * g][1], bF[2 * g + 1][0], bF[2 * g + 1][1],
                      wb1 + bRowOff[g] + bo);
#pragma unroll
            for (int j = 0; j < 8; j++) {
                mma16816(acc[0][j], aF[0], bF[j]);
                mma16816(acc[1][j], aF[1], bF[j]);
            }
        }

        // ---- bias + relu -> fp16 layer-2 A fragments (registers only) ----
        uint32_t A2[2][4][4];
#pragma unroll
        for (int m = 0; m < 2; m++)
#pragma unroll
            for (int k2 = 0; k2 < 4; k2++) {
                const int j0 = 2 * k2, j1 = 2 * k2 + 1;
                const int c0 = j0 * 8 + 2 * tig;
                const int c1 = j1 * 8 + 2 * tig;
                const float bb00 = b1v[c0], bb01 = b1v[c0 + 1];
                const float bb10 = b1v[c1], bb11 = b1v[c1 + 1];
                A2[m][k2][0] = packh2(fmaxf(acc[m][j0][0] + bb00, 0.f),
                                      fmaxf(acc[m][j0][1] + bb01, 0.f));
                A2[m][k2][1] = packh2(fmaxf(acc[m][j0][2] + bb00, 0.f),
                                      fmaxf(acc[m][j0][3] + bb01, 0.f));
                A2[m][k2][2] = packh2(fmaxf(acc[m][j1][0] + bb10, 0.f),
                                      fmaxf(acc[m][j1][1] + bb11, 0.f));
                A2[m][k2][3] = packh2(fmaxf(acc[m][j1][2] + bb10, 0.f),
                                      fmaxf(acc[m][j1][3] + bb11, 0.f));
            }

        // ---- Layer 2 ----
#pragma unroll
        for (int m = 0; m < 2; m++)
#pragma unroll
            for (int j = 0; j < 8; j++)
#pragma unroll
                for (int rr = 0; rr < 4; rr++) acc[m][j][rr] = 0.0f;

#pragma unroll
        for (int k2 = 0; k2 < 4; k2++) {
            const uint32_t bo = bLow ^ (uint32_t)(k2 * 32);
            uint32_t bF[8][2];
#pragma unroll
            for (int g = 0; g < 4; g++)
                ldsm4(bF[2 * g][0], bF[2 * g][1], bF[2 * g + 1][0], bF[2 * g + 1][1],
                      wb2 + bRowOff[g] + bo);
#pragma unroll
            for (int j = 0; j < 8; j++) {
                mma16816(acc[0][j], A2[0][k2], bF[j]);
                mma16816(acc[1][j], A2[1][k2], bF[j]);
            }
        }

        // ---- Layer 3: bias + relu + dot(w3) + quad reduce + store ----
#pragma unroll
        for (int m = 0; m < 2; m++) {
            float p0 = 0.f, p1 = 0.f;
#pragma unroll
            for (int j = 0; j < 8; j++) {
                const int c = 8 * j + 2 * tig;
                const float w0 = w3v[c], w1 = w3v[c + 1];
                const float bb0 = b2v[c], bb1 = b2v[c + 1];
                p0 += fmaxf(acc[m][j][0] + bb0, 0.f) * w0
                    + fmaxf(acc[m][j][1] + bb1, 0.f) * w1;
                p1 += fmaxf(acc[m][j][2] + bb0, 0.f) * w0
                    + fmaxf(acc[m][j][3] + bb1, 0.f) * w1;
            }
            p0 += __shfl_xor_sync(0xFFFFFFFFu, p0, 1);
            p0 += __shfl_xor_sync(0xFFFFFFFFu, p0, 2);
            p1 += __shfl_xor_sync(0xFFFFFFFFu, p1, 1);
            p1 += __shfl_xor_sync(0xFFFFFFFFu, p1, 2);
            if (tig == 0) {
                const int row = rowBase + warp * 32 + m * 16 + grp;
                if (row < B)     out[(size_t)row * 64 + (i + 1)]       = p0 + b3v;
                if (row + 8 < B) out[(size_t)(row + 8) * 64 + (i + 1)] = p1 + b3v;
            }
        }
    }

    // dim-0 column (batch-constant), written by chunk-0 CTAs only
    if (chunk == 0 && rowBase + tid < B) out[(size_t)(rowBase + tid) * 64] = o0;
}

// ============================================================================
// Launch
// ============================================================================
extern "C" void kernel_launch(void* const* d_in, const int* in_sizes, int n_in,
                              void* d_out, int out_size) {
    const float* x   = (const float*)d_in[0];
    const float* W1  = (const float*)d_in[1];
    const float* b1  = (const float*)d_in[2];
    const float* W2  = (const float*)d_in[3];
    const float* b2  = (const float*)d_in[4];
    const float* W3  = (const float*)d_in[5];
    const float* b3  = (const float*)d_in[6];
    const float* w01 = (const float*)d_in[7];
    const float* b01 = (const float*)d_in[8];
    const float* w02 = (const float*)d_in[9];
    const float* b02 = (const float*)d_in[10];
    const float* w03 = (const float*)d_in[11];
    const float* b03 = (const float*)d_in[12];
    float* out = (float*)d_out;

    const int B = in_sizes[0] / DK;

    prep_weights_kernel<<<(NI * DK * HN + 255) / 256, 256>>>(W1, W2);
    prep_bias_kernel<<<(NI * 208 + 255) / 256, 256>>>(b1, b2, W3, b3);
    prep_dim0_kernel<<<1, 64>>>(w01, b01, w02, b02, w03, b03);

    static bool attr_set = false;
    if (!attr_set) {
        cudaFuncSetAttribute(mlplist_main_kernel,
                             cudaFuncAttributeMaxDynamicSharedMemorySize, SMEM_BYTES);
        attr_set = true;
    }
    dim3 grid((B + 127) / 128, NCHUNK);
    mlplist_main_kernel<<<grid, 128, SMEM_BYTES>>>(x, out, B);
}

// round 13
// speedup vs baseline: 3.7390x; 1.0935x over previous
#include <cuda_runtime.h>
#include <cuda_fp16.h>
#include <cstdint>

// ============================================================================
// MLPList: B=32768 rows, 63 stacked MLPs (64->64->64->1), causal input mask.
// R12 = R11 + half2 epilogues (biases pre-packed fp16x2, HADD2/HMAX2) and
// layer-3 dot executed as MMA (w3 B-fragment synthesized in registers).
// fp16 1-MMA-per-product, ldmatrix.x4 loads, 4-way i-split, 3 CTAs/SM.
// ============================================================================
#define NI 63
#define DK 64
#define HN 64
#define NCHUNK 4

__device__ __align__(16) unsigned char g_wpack[NI * 16384]; // W1,W2 fp16 (8KB each)
__device__ __align__(16) uint32_t g_bpack[NI * 128];        // b1h2[32],b2h2[32],w3h2[32],b3,pad
__device__ float g_o0;

// ---------------------------------------------------------------------------
__device__ __forceinline__ uint32_t smem_u32(const void* p) {
    uint32_t a;
    asm("{ .reg .u64 t; cvta.to.shared.u64 t, %1; cvt.u32.u64 %0, t; }"
        : "=r"(a) : "l"(p));
    return a;
}

__device__ __forceinline__ uint32_t packh2(float a, float b) {
    __half2 h = __floats2half2_rn(a, b);
    return *(uint32_t*)&h;
}

// relu(fp16(a,b) + bias2) in half2, returned as packed u32
__device__ __forceinline__ uint32_t relu_bias_h2(float a, float b, uint32_t bias2) {
    __half2 v = __floats2half2_rn(a, b);
    __half2 bb = *(__half2*)&bias2;
    __half2 z = __float2half2_rn(0.f);
    __half2 r = __hmax2(__hadd2(v, bb), z);
    return *(uint32_t*)&r;
}

__device__ __forceinline__ void mma16816(float* d, const uint32_t* a, const uint32_t* b) {
    asm volatile(
        "mma.sync.aligned.m16n8k16.row.col.f32.f16.f16.f32 "
        "{%0,%1,%2,%3}, {%4,%5,%6,%7}, {%8,%9}, {%0,%1,%2,%3};"
        : "+f"(d[0]), "+f"(d[1]), "+f"(d[2]), "+f"(d[3])
        : "r"(a[0]), "r"(a[1]), "r"(a[2]), "r"(a[3]), "r"(b[0]), "r"(b[1]));
}

__device__ __forceinline__ void ldsm4(uint32_t& r0, uint32_t& r1, uint32_t& r2,
                                      uint32_t& r3, uint32_t addr) {
    asm volatile("ldmatrix.sync.aligned.m8n8.x4.shared.b16 {%0,%1,%2,%3}, [%4];"
                 : "=r"(r0), "=r"(r1), "=r"(r2), "=r"(r3) : "r"(addr));
}

// ============================================================================
// Prep kernels
// ============================================================================
__global__ void prep_weights_kernel(const float* __restrict__ W1,
                                    const float* __restrict__ W2) {
    int idx = blockIdx.x * blockDim.x + threadIdx.x;
    if (idx >= NI * DK * HN) return;
    int i = idx >> 12;
    int n = (idx >> 6) & 63;
    int k = idx & 63;
    uint32_t off = (uint32_t)(n * 128) + (uint32_t)((k * 2) ^ ((n & 7) << 4));
    unsigned char* base = g_wpack + (size_t)i * 16384;

    float v1 = (k <= i) ? W1[((size_t)i * DK + k) * HN + n] : 0.0f;
    *(__half*)(base + 0 * 8192 + off) = __float2half_rn(v1);

    float v2 = W2[((size_t)i * HN + k) * HN + n];
    *(__half*)(base + 1 * 8192 + off) = __float2half_rn(v2);
}

// Bias pack per i (512B): [0,32) b1 half2 pairs, [32,64) b2, [64,96) w3, [96] b3 bits
__global__ void prep_bias_kernel(const float* __restrict__ b1, const float* __restrict__ b2,
                                 const float* __restrict__ W3, const float* __restrict__ b3) {
    int idx = blockIdx.x * blockDim.x + threadIdx.x;
    if (idx >= NI * 128) return;
    int i = idx >> 7, t = idx & 127;
    uint32_t v = 0;
    if (t < 32)       v = packh2(b1[i * 64 + 2 * t],        b1[i * 64 + 2 * t + 1]);
    else if (t < 64)  v = packh2(b2[i * 64 + 2 * (t - 32)], b2[i * 64 + 2 * (t - 32) + 1]);
    else if (t < 96)  v = packh2(W3[i * 64 + 2 * (t - 64)], W3[i * 64 + 2 * (t - 64) + 1]);
    else if (t == 96) v = __float_as_uint(b3[i]);
    g_bpack[i * 128 + t] = v;
}

__global__ void prep_dim0_kernel(const float* __restrict__ w01, const float* __restrict__ b01,
                                 const float* __restrict__ w02, const float* __restrict__ b02,
                                 const float* __restrict__ w03, const float* __restrict__ b03) {
    __shared__ float h0s[64];
    __shared__ float ps[64];
    int h = threadIdx.x;
    float a = b01[h];
#pragma unroll
    for (int t = 0; t < 10; t++) {
        float v = 0.1f * (-5.0f + (float)t * (10.0f / 9.0f));
        a = fmaf(v, w01[t * 64 + h], a);
    }
    h0s[h] = fmaxf(a, 0.0f);
    __syncthreads();
    float a2 = b02[h];
#pragma unroll
    for (int k = 0; k < 64; k++) a2 = fmaf(h0s[k], w02[k * 64 + h], a2);
    ps[h] = fmaxf(a2, 0.0f) * w03[h];
    __syncthreads();
    if (h == 0) {
        float s = b03[0];
        for (int k = 0; k < 64; k++) s += ps[k];
        g_o0 = s;
    }
}

// ============================================================================
// Main kernel
// ============================================================================
constexpr int OFF_X    = 0;              // 128x64 fp16 X tile (16KB, swizzled)
constexpr int OFF_W    = 16384;          // 2 x 16384B (W1, W2)
constexpr int OFF_BIAS = 49152;          // 2 x 512B
constexpr int SMEM_BYTES = 50176;

__device__ __forceinline__ void stage_i(char* smem, int i, int buf, int tid) {
    const unsigned char* src = g_wpack + (size_t)i * 16384;
    uint32_t dst = smem_u32(smem + OFF_W + buf * 16384);
#pragma unroll
    for (int j = 0; j < 8; j++) {
        int c = tid + j * 128;   // 1024 chunks of 16B = 16KB
        asm volatile("cp.async.cg.shared.global [%0], [%1], 16;"
                     :: "r"(dst + c * 16), "l"(src + (size_t)c * 16));
    }
    if (tid < 32) {
        const unsigned char* bsrc = (const unsigned char*)(g_bpack + (size_t)i * 128);
        uint32_t bdst = smem_u32(smem + OFF_BIAS + buf * 512) + tid * 16;
        asm volatile("cp.async.cg.shared.global [%0], [%1], 16;"
                     :: "r"(bdst), "l"(bsrc + tid * 16));
    }
    asm volatile("cp.async.commit_group;" ::: "memory");
}

__global__ void __launch_bounds__(128, 3)
mlplist_main_kernel(const float* __restrict__ x, float* __restrict__ out, int B) {
    extern __shared__ char smem[];
    const int tid  = threadIdx.x;
    const int warp = tid >> 5, lane = tid & 31;
    const int tig  = lane & 3, grp = lane >> 2;
    const int q    = lane >> 3, r = lane & 7;    // ldmatrix lane decomposition
    const int rowBase = blockIdx.x * 128;
    const int chunk = blockIdx.y;
    const int niters = (NI - chunk + NCHUNK - 1) / NCHUNK;   // 16,16,16,15
    const float o0 = g_o0;

    // ---- ldmatrix per-lane address constants ----
    const uint32_t xbase = smem_u32(smem + OFF_X);
    uint32_t aBase[2];
#pragma unroll
    for (int m = 0; m < 2; m++) {
        const int arow = warp * 32 + m * 16 + (q & 1) * 8 + r;
        aBase[m] = xbase + (uint32_t)(arow * 128);
    }
    const uint32_t aLow = (uint32_t)(((q >> 1) * 16) ^ (r << 4));
    uint32_t bRowOff[4];
#pragma unroll
    for (int g = 0; g < 4; g++)
        bRowOff[g] = (uint32_t)((16 * g + (q >> 1) * 8 + r) * 128);
    const uint32_t bLow = (uint32_t)(((q & 1) * 16) ^ (r << 4));

    // ---- load X tile -> fp16 swizzled tile (thread = row) ----
    {
        const int row = rowBase + tid;
        if (row < B) {
            const float4* xr = (const float4*)(x + (size_t)row * DK);
#pragma unroll
            for (int c = 0; c < 8; c++) {
                float4 f0 = xr[2 * c], f1 = xr[2 * c + 1];
                uint4 hp;
                hp.x = packh2(f0.x, f0.y);
                hp.y = packh2(f0.z, f0.w);
                hp.z = packh2(f1.x, f1.y);
                hp.w = packh2(f1.z, f1.w);
                uint32_t off = (uint32_t)(tid * 128) + (uint32_t)((c * 16) ^ ((tid & 7) << 4));
                *(uint4*)(smem + OFF_X + off) = hp;
            }
        }
    }

    stage_i(smem, chunk, 0, tid);

    for (int t = 0; t < niters; t++) {
        const int i = chunk + t * NCHUNK;
        const int buf = t & 1;
        __syncthreads();
        if (t + 1 < niters) {
            stage_i(smem, i + NCHUNK, buf ^ 1, tid);
            asm volatile("cp.async.wait_group 1;" ::: "memory");
        } else {
            asm volatile("cp.async.wait_group 0;" ::: "memory");
        }
        __syncthreads();

        const uint32_t wb1 = smem_u32(smem + OFF_W + buf * 16384);      // W1
        const uint32_t wb2 = wb1 + 8192;                                 // W2
        const uint32_t* bias_u = (const uint32_t*)(smem + OFF_BIAS + buf * 512);
        const uint32_t* b1h2 = bias_u;          // 32 half2
        const uint32_t* b2h2 = bias_u + 32;
        const uint32_t* w3h2 = bias_u + 64;
        const float b3v = __uint_as_float(bias_u[96]);

        // w3 B-fragment per k-step (n=0 column only -> grp==0 lanes hold data)
        uint32_t w3b[4][2];
#pragma unroll
        for (int kk = 0; kk < 4; kk++) {
            w3b[kk][0] = (grp == 0) ? w3h2[kk * 8 + tig]     : 0u;
            w3b[kk][1] = (grp == 0) ? w3h2[kk * 8 + 4 + tig] : 0u;
        }

        float acc[2][8][4];
#pragma unroll
        for (int m = 0; m < 2; m++)
#pragma unroll
            for (int j = 0; j < 8; j++)
#pragma unroll
                for (int rr = 0; rr < 4; rr++) acc[m][j][rr] = 0.0f;

        // ---- Layer 1: acc += X_fp16 @ W1_fp16^T (masked K chunks skipped) ----
        const int kt1 = (i >> 4) + 1;
        for (int kt = 0; kt < kt1; kt++) {
            const uint32_t kb = (uint32_t)(kt * 32);
            const uint32_t ao = aLow ^ kb;
            const uint32_t bo = bLow ^ kb;
            uint32_t aF[2][4];
            ldsm4(aF[0][0], aF[0][1], aF[0][2], aF[0][3], aBase[0] + ao);
            ldsm4(aF[1][0], aF[1][1], aF[1][2], aF[1][3], aBase[1] + ao);
            uint32_t bF[8][2];
#pragma unroll
            for (int g = 0; g < 4; g++)
                ldsm4(bF[2 * g][0], bF[2 * g][1], bF[2 * g + 1][0], bF[2 * g + 1][1],
                      wb1 + bRowOff[g] + bo);
#pragma unroll
            for (int j = 0; j < 8; j++) {
                mma16816(acc[0][j], aF[0], bF[j]);
                mma16816(acc[1][j], aF[1], bF[j]);
            }
        }

        // ---- bias + relu (half2) -> fp16 layer-2 A fragments ----
        uint32_t A2[2][4][4];
#pragma unroll
        for (int m = 0; m < 2; m++)
#pragma unroll
            for (int k2 = 0; k2 < 4; k2++) {
                const int j0 = 2 * k2, j1 = 2 * k2 + 1;
                const uint32_t bb0 = b1h2[j0 * 4 + tig];
                const uint32_t bb1 = b1h2[j1 * 4 + tig];
                A2[m][k2][0] = relu_bias_h2(acc[m][j0][0], acc[m][j0][1], bb0);
                A2[m][k2][1] = relu_bias_h2(acc[m][j0][2], acc[m][j0][3], bb0);
                A2[m][k2][2] = relu_bias_h2(acc[m][j1][0], acc[m][j1][1], bb1);
                A2[m][k2][3] = relu_bias_h2(acc[m][j1][2], acc[m][j1][3], bb1);
            }

        // ---- Layer 2 ----
#pragma unroll
        for (int m = 0; m < 2; m++)
#pragma unroll
            for (int j = 0; j < 8; j++)
#pragma unroll
                for (int rr = 0; rr < 4; rr++) acc[m][j][rr] = 0.0f;

#pragma unroll
        for (int k2 = 0; k2 < 4; k2++) {
            const uint32_t bo = bLow ^ (uint32_t)(k2 * 32);
            uint32_t bF[8][2];
#pragma unroll
            for (int g = 0; g < 4; g++)
                ldsm4(bF[2 * g][0], bF[2 * g][1], bF[2 * g + 1][0], bF[2 * g + 1][1],
                      wb2 + bRowOff[g] + bo);
#pragma unroll
            for (int j = 0; j < 8; j++) {
                mma16816(acc[0][j], A2[0][k2], bF[j]);
                mma16816(acc[1][j], A2[1][k2], bF[j]);
            }
        }

        // ---- Layer 3: bias+relu (half2) -> A3 fragments -> MMA with w3 ----
#pragma unroll
        for (int m = 0; m < 2; m++) {
            uint32_t A3[4][4];
#pragma unroll
            for (int kk = 0; kk < 4; kk++) {
                const int j0 = 2 * kk, j1 = 2 * kk + 1;
                const uint32_t bb0 = b2h2[j0 * 4 + tig];
                const uint32_t bb1 = b2h2[j1 * 4 + tig];
                A3[kk][0] = relu_bias_h2(acc[m][j0][0], acc[m][j0][1], bb0);
                A3[kk][1] = relu_bias_h2(acc[m][j0][2], acc[m][j0][3], bb0);
                A3[kk][2] = relu_bias_h2(acc[m][j1][0], acc[m][j1][1], bb1);
                A3[kk][3] = relu_bias_h2(acc[m][j1][2], acc[m][j1][3], bb1);
            }
            float d3[4] = {0.f, 0.f, 0.f, 0.f};
#pragma unroll
            for (int kk = 0; kk < 4; kk++)
                mma16816(d3, A3[kk], w3b[kk]);
            // D col 0 lives on tig==0 lanes: d3[0]=row grp, d3[2]=row grp+8
            if (tig == 0) {
                const int row = rowBase + warp * 32 + m * 16 + grp;
                if (row < B)     out[(size_t)row * 64 + (i + 1)]       = d3[0] + b3v;
                if (row + 8 < B) out[(size_t)(row + 8) * 64 + (i + 1)] = d3[2] + b3v;
            }
        }
    }

    // dim-0 column (batch-constant), written by chunk-0 CTAs only
    if (chunk == 0 && rowBase + tid < B) out[(size_t)(rowBase + tid) * 64] = o0;
}

// ============================================================================
// Launch
// ============================================================================
extern "C" void kernel_launch(void* const* d_in, const int* in_sizes, int n_in,
                              void* d_out, int out_size) {
    const float* x   = (const float*)d_in[0];
    const float* W1  = (const float*)d_in[1];
    const float* b1  = (const float*)d_in[2];
    const float* W2  = (const float*)d_in[3];
    const float* b2  = (const float*)d_in[4];
    const float* W3  = (const float*)d_in[5];
    const float* b3  = (const float*)d_in[6];
    const float* w01 = (const float*)d_in[7];
    const float* b01 = (const float*)d_in[8];
    const float* w02 = (const float*)d_in[9];
    const float* b02 = (const float*)d_in[10];
    const float* w03 = (const float*)d_in[11];
    const float* b03 = (const float*)d_in[12];
    float* out = (float*)d_out;

    const int B = in_sizes[0] / DK;

    prep_weights_kernel<<<(NI * DK * HN + 255) / 256, 256>>>(W1, W2);
    prep_bias_kernel<<<(NI * 128 + 255) / 256, 256>>>(b1, b2, W3, b3);
    prep_dim0_kernel<<<1, 64>>>(w01, b01, w02, b02, w03, b03);

    static bool attr_set = false;
    if (!attr_set) {
        cudaFuncSetAttribute(mlplist_main_kernel,
                             cudaFuncAttributeMaxDynamicSharedMemorySize, SMEM_BYTES);
        attr_set = true;
    }
    dim3 grid((B + 127) / 128, NCHUNK);
    mlplist_main_kernel<<<grid, 128, SMEM_BYTES>>>(x, out, B);
}